// round 6
// baseline (speedup 1.0000x reference)
#include <cuda_runtime.h>
#include <cuda_fp16.h>

#define NMAX 100000
#define EMAX 1600000
#define HDIM 64
#define HC 32
#define NLAYERS 3
#define BN_EPS 1e-5f
#define SCAN_BLK 1024
#define SCAN_MAXB 128

// ---- scratch (device globals; no allocation allowed) ----
__device__ __half2 g_hs2[NMAX * 32];       // (h @ W) * dinv[row], fp16 pairs
__device__ float g_agg[NMAX * HDIM];       // pre-BN aggregated features (fp32)
__device__ int   g_cnt [NMAX];             // in-degree counts (left at 0 on exit)
__device__ float g_dinv[NMAX];             // (deg+1)^-1/2
__device__ int   g_row [NMAX + 1];         // CSR row pointers (by dst)
__device__ int   g_cur [NMAX];             // bucket cursors
__device__ int   g_srcs[EMAX];             // src node ids sorted by dst
__device__ volatile int g_part[SCAN_MAXB]; // lookback partials (total+1)
__device__ float g_stats[NLAYERS][2 * HDIM]; // per-layer channel sum, sumsq

static __device__ __forceinline__ unsigned s2u(const void* p) {
    return (unsigned)__cvta_generic_to_shared(p);
}

// ---------------------------------------------------------------------------
// count in-degrees; block 0 also zeroes lookback partials + BN stats
__global__ void k_count_deg(const int* __restrict__ dst, int e) {
    int i = blockIdx.x * blockDim.x + threadIdx.x;
    if (blockIdx.x == 0) {
        if (threadIdx.x < SCAN_MAXB) *(int*)&g_part[threadIdx.x] = 0;
        for (int j = threadIdx.x; j < NLAYERS * 2 * HDIM; j += 256)
            (&g_stats[0][0])[j] = 0.0f;
    }
    if (i < e) atomicAdd(&g_cnt[dst[i]], 1);
}

// fused scan: dinv + exclusive prefix (decoupled lookback) -> g_row, g_cur
__global__ void k_scan_fused(int n, int e) {
    __shared__ int sh[256];
    int tid = threadIdx.x, b = blockIdx.x;
    int base = b * SCAN_BLK + tid * 4;

    int v[4]; int mine = 0;
    if (base + 4 <= n) {
        int4 c = *reinterpret_cast<const int4*>(&g_cnt[base]);
        v[0] = c.x; v[1] = c.y; v[2] = c.z; v[3] = c.w;
        g_dinv[base + 0] = rsqrtf((float)c.x + 1.0f);
        g_dinv[base + 1] = rsqrtf((float)c.y + 1.0f);
        g_dinv[base + 2] = rsqrtf((float)c.z + 1.0f);
        g_dinv[base + 3] = rsqrtf((float)c.w + 1.0f);
        mine = c.x + c.y + c.z + c.w;
    } else {
#pragma unroll
        for (int k = 0; k < 4; k++) {
            v[k] = 0;
            if (base + k < n) {
                int c = g_cnt[base + k];
                v[k] = c;
                g_dinv[base + k] = rsqrtf((float)c + 1.0f);
                mine += c;
            }
        }
    }

    sh[tid] = mine;
    __syncthreads();
    for (int o = 1; o < 256; o <<= 1) {
        int t = (tid >= o) ? sh[tid - o] : 0;
        __syncthreads();
        sh[tid] += t;
        __syncthreads();
    }
    int excl = sh[tid] - mine;
    int total = sh[255];

    if (tid == 0) atomicExch((int*)&g_part[b], total + 1);
    int pref = 0;
    for (int i = tid; i < b; i += 256) {
        int p;
        while ((p = g_part[i]) == 0) {}
        pref += p - 1;
    }
    __syncthreads();
    sh[tid] = pref;
    __syncthreads();
    for (int o = 128; o > 0; o >>= 1) {
        if (tid < o) sh[tid] += sh[tid + o];
        __syncthreads();
    }
    int off = sh[0] + excl;

#pragma unroll
    for (int k = 0; k < 4; k++) {
        int idx = base + k;
        if (idx < n) {
            g_row[idx] = off;
            g_cur[idx] = off;
            off += v[k];
        }
    }
    if (b == 0 && tid == 0) g_row[n] = e;
}

// counting-sort bucket placement; also re-zero g_cnt for the next replay
__global__ void k_bucket(const int* __restrict__ ei, int e, int n) {
    int i = blockIdx.x * blockDim.x + threadIdx.x;
    if (i < n) g_cnt[i] = 0;
    if (i >= e) return;
    int s = ei[i];
    int d = ei[e + i];
    int pos = atomicAdd(&g_cur[d], 1);
    g_srcs[pos] = s;
}

// ---------------------------------------------------------------------------
// Tensor-core GEMM: 128 nodes x 64 cols per block, 8 warps (16 rows each).
// Restructured for minimal register liveness: epilogue inside nt-pair loop.
#define GROWS 128
#define ASTRIDE 72   // halves; 144B rows: 16B aligned, ldmatrix conflict-free
__global__ void __launch_bounds__(256, 1) k_gemm_mma(
    const float* __restrict__ W, int n, int layer,
    const float* __restrict__ x, const float* __restrict__ Win,
    const float* __restrict__ bin,
    const float* __restrict__ gamma, const float* __restrict__ beta) {
    __shared__ __half Asm[GROWS * ASTRIDE];
    __shared__ __half Wsm[HDIM * ASTRIDE];
    __shared__ float s_sc[HDIM], s_sf[HDIM];

    int tid = threadIdx.x;
    int node0 = blockIdx.x * GROWS;

    if (layer > 0) {
        if (tid < HDIM) {
            float inv_n = 1.0f / (float)n;
            float mean = g_stats[layer - 1][tid] * inv_n;
            float var = g_stats[layer - 1][HDIM + tid] * inv_n - mean * mean;
            float inv = rsqrtf(var + BN_EPS);
            float sc = gamma[tid] * inv;
            s_sc[tid] = sc;
            s_sf[tid] = beta[tid] - mean * sc;
        }
        __syncthreads();
    }

    // W (64x64 fp32) -> fp16 smem
    for (int i = tid; i < HDIM * HDIM / 4; i += 256) {
        float4 w = *reinterpret_cast<const float4*>(&W[i * 4]);
        int r = i >> 4;
        int c = (i * 4) & 63;
        __half2 h0 = __floats2half2_rn(w.x, w.y);
        __half2 h1 = __floats2half2_rn(w.z, w.w);
        uint2 pk;
        pk.x = *reinterpret_cast<unsigned*>(&h0);
        pk.y = *reinterpret_cast<unsigned*>(&h1);
        *reinterpret_cast<uint2*>(&Wsm[r * ASTRIDE + c]) = pk;
    }

    // A tile (128 x 64) -> fp16 smem, fused BN/relu or input-proj
#pragma unroll
    for (int it = 0; it < 8; it++) {
        int idx = tid + it * 256;
        int row = idx >> 4;
        int c4 = (idx & 15) * 4;
        int node = node0 + row;
        float4 v = make_float4(0.f, 0.f, 0.f, 0.f);
        if (node < n) {
            if (layer > 0) {
                v = *reinterpret_cast<const float4*>(&g_agg[node * HDIM + c4]);
                v.x = fmaf(v.x, s_sc[c4 + 0], s_sf[c4 + 0]);
                v.y = fmaf(v.y, s_sc[c4 + 1], s_sf[c4 + 1]);
                v.z = fmaf(v.z, s_sc[c4 + 2], s_sf[c4 + 2]);
                v.w = fmaf(v.w, s_sc[c4 + 3], s_sf[c4 + 3]);
            } else {
                v = *reinterpret_cast<const float4*>(&bin[c4]);
#pragma unroll
                for (int k = 0; k < 5; k++) {
                    float xv = __ldg(&x[node * 5 + k]);
                    float4 w = *reinterpret_cast<const float4*>(&Win[k * HDIM + c4]);
                    v.x = fmaf(xv, w.x, v.x);
                    v.y = fmaf(xv, w.y, v.y);
                    v.z = fmaf(xv, w.z, v.z);
                    v.w = fmaf(xv, w.w, v.w);
                }
            }
            v.x = fmaxf(v.x, 0.f); v.y = fmaxf(v.y, 0.f);
            v.z = fmaxf(v.z, 0.f); v.w = fmaxf(v.w, 0.f);
        }
        __half2 h0 = __floats2half2_rn(v.x, v.y);
        __half2 h1 = __floats2half2_rn(v.z, v.w);
        uint2 pk;
        pk.x = *reinterpret_cast<unsigned*>(&h0);
        pk.y = *reinterpret_cast<unsigned*>(&h1);
        *reinterpret_cast<uint2*>(&Asm[row * ASTRIDE + c4]) = pk;
    }
    __syncthreads();

    int warp = tid >> 5, lane = tid & 31;
    int wrow = warp * 16;
    int r15 = lane & 15;

    // A fragments for all 4 k-steps (m16k16 each): 16 regs
    unsigned a[4][4];
    {
        int cb = (lane >> 4) << 3;
#pragma unroll
        for (int ks = 0; ks < 4; ks++) {
            unsigned addr = s2u(&Asm[(wrow + r15) * ASTRIDE + ks * 16 + cb]);
            asm volatile("ldmatrix.sync.aligned.m8n8.x4.shared.b16 {%0,%1,%2,%3}, [%4];"
                         : "=r"(a[ks][0]), "=r"(a[ks][1]), "=r"(a[ks][2]), "=r"(a[ks][3])
                         : "r"(addr));
        }
    }

    int gr = lane >> 2;
    int qp = lane & 3;
    int node_a = node0 + wrow + gr;
    int node_b = node_a + 8;
    float dia = (node_a < n) ? g_dinv[node_a] : 0.f;
    float dib = (node_b < n) ? g_dinv[node_b] : 0.f;

    // nt pairs: compute 2 n-tiles (16 cols) at a time, epilogue immediately.
#pragma unroll
    for (int ntp = 0; ntp < 4; ntp++) {
        float acc0[4] = {0.f, 0.f, 0.f, 0.f};
        float acc1[4] = {0.f, 0.f, 0.f, 0.f};
#pragma unroll
        for (int ks = 0; ks < 4; ks++) {
            unsigned b0, b1, b2, b3;
            unsigned baddr = s2u(&Wsm[(ks * 16 + r15) * ASTRIDE +
                                      ntp * 16 + ((lane >> 4) << 3)]);
            asm volatile("ldmatrix.sync.aligned.m8n8.x4.trans.shared.b16 {%0,%1,%2,%3}, [%4];"
                         : "=r"(b0), "=r"(b1), "=r"(b2), "=r"(b3) : "r"(baddr));
            asm volatile(
                "mma.sync.aligned.m16n8k16.row.col.f32.f16.f16.f32 "
                "{%0,%1,%2,%3}, {%4,%5,%6,%7}, {%8,%9}, {%0,%1,%2,%3};"
                : "+f"(acc0[0]), "+f"(acc0[1]), "+f"(acc0[2]), "+f"(acc0[3])
                : "r"(a[ks][0]), "r"(a[ks][1]), "r"(a[ks][2]), "r"(a[ks][3]),
                  "r"(b0), "r"(b1));
            asm volatile(
                "mma.sync.aligned.m16n8k16.row.col.f32.f16.f16.f32 "
                "{%0,%1,%2,%3}, {%4,%5,%6,%7}, {%8,%9}, {%0,%1,%2,%3};"
                : "+f"(acc1[0]), "+f"(acc1[1]), "+f"(acc1[2]), "+f"(acc1[3])
                : "r"(a[ks][0]), "r"(a[ks][1]), "r"(a[ks][2]), "r"(a[ks][3]),
                  "r"(b2), "r"(b3));
        }
        int nt0 = 2 * ntp, nt1 = 2 * ntp + 1;
        if (node_a < n) {
            g_hs2[node_a * 32 + nt0 * 4 + qp] =
                __floats2half2_rn(acc0[0] * dia, acc0[1] * dia);
            g_hs2[node_a * 32 + nt1 * 4 + qp] =
                __floats2half2_rn(acc1[0] * dia, acc1[1] * dia);
        }
        if (node_b < n) {
            g_hs2[node_b * 32 + nt0 * 4 + qp] =
                __floats2half2_rn(acc0[2] * dib, acc0[3] * dib);
            g_hs2[node_b * 32 + nt1 * 4 + qp] =
                __floats2half2_rn(acc1[2] * dib, acc1[3] * dib);
        }
    }
}

// ---------------------------------------------------------------------------
// pull-based aggregation + BN stats. Half-warps process 2 edges concurrently:
// lane = half*16 + lane16; lane16 covers channels [4*lane16, 4*lane16+4) via uint2.
#define AGG_WARPS 8
#define NODES_PER_WARP 8
__global__ void k_aggregate(int n, int layer) {
    __shared__ float s_sum[HDIM], s_sq[HDIM];
    int tid = threadIdx.x, lane = tid & 31, warp = tid >> 5;
    int lane16 = lane & 15, half = lane >> 4;
    if (tid < HDIM) { s_sum[tid] = 0.f; s_sq[tid] = 0.f; }
    __syncthreads();

    const uint2* hs = reinterpret_cast<const uint2*>(g_hs2);  // node*16 + lane16
    float ls[4] = {0.f, 0.f, 0.f, 0.f};
    float lq[4] = {0.f, 0.f, 0.f, 0.f};
    int node0 = (blockIdx.x * AGG_WARPS + warp) * NODES_PER_WARP;

    for (int i = 0; i < NODES_PER_WARP; i++) {
        int node = node0 + i;
        if (node >= n) break;
        int beg = g_row[node], end = g_row[node + 1];
        float a0 = 0.f, a1 = 0.f, a2 = 0.f, a3 = 0.f;
        int j = beg;
        // 4 pairs unrolled = 8 edges per iteration
        for (; j + 8 <= end; j += 8) {
            int ss[4];
#pragma unroll
            for (int u = 0; u < 4; u++) ss[u] = g_srcs[j + 2 * u + half];
            uint2 rv[4];
#pragma unroll
            for (int u = 0; u < 4; u++) rv[u] = hs[ss[u] * 16 + lane16];
#pragma unroll
            for (int u = 0; u < 4; u++) {
                float2 f0 = __half22float2(*reinterpret_cast<__half2*>(&rv[u].x));
                float2 f1 = __half22float2(*reinterpret_cast<__half2*>(&rv[u].y));
                a0 += f0.x; a1 += f0.y; a2 += f1.x; a3 += f1.y;
            }
        }
        for (; j + 2 <= end; j += 2) {
            int s = g_srcs[j + half];
            uint2 rv = hs[s * 16 + lane16];
            float2 f0 = __half22float2(*reinterpret_cast<__half2*>(&rv.x));
            float2 f1 = __half22float2(*reinterpret_cast<__half2*>(&rv.y));
            a0 += f0.x; a1 += f0.y; a2 += f1.x; a3 += f1.y;
        }
        if (j < end && half == 0) {   // odd remainder edge
            int s = g_srcs[j];
            uint2 rv = hs[s * 16 + lane16];
            float2 f0 = __half22float2(*reinterpret_cast<__half2*>(&rv.x));
            float2 f1 = __half22float2(*reinterpret_cast<__half2*>(&rv.y));
            a0 += f0.x; a1 += f0.y; a2 += f1.x; a3 += f1.y;
        }
        // merge half-warps
        a0 += __shfl_xor_sync(0xFFFFFFFFu, a0, 16);
        a1 += __shfl_xor_sync(0xFFFFFFFFu, a1, 16);
        a2 += __shfl_xor_sync(0xFFFFFFFFu, a2, 16);
        a3 += __shfl_xor_sync(0xFFFFFFFFu, a3, 16);

        if (half == 0) {
            uint2 sv = hs[node * 16 + lane16];
            float2 f0 = __half22float2(*reinterpret_cast<__half2*>(&sv.x));
            float2 f1 = __half22float2(*reinterpret_cast<__half2*>(&sv.y));
            float di = g_dinv[node];
            a0 = (a0 + f0.x) * di;
            a1 = (a1 + f0.y) * di;
            a2 = (a2 + f1.x) * di;
            a3 = (a3 + f1.y) * di;
            float4 o; o.x = a0; o.y = a1; o.z = a2; o.w = a3;
            *reinterpret_cast<float4*>(&g_agg[node * HDIM + lane16 * 4]) = o;
            ls[0] += a0; lq[0] = fmaf(a0, a0, lq[0]);
            ls[1] += a1; lq[1] = fmaf(a1, a1, lq[1]);
            ls[2] += a2; lq[2] = fmaf(a2, a2, lq[2]);
            ls[3] += a3; lq[3] = fmaf(a3, a3, lq[3]);
        }
    }

    if (half == 0) {
#pragma unroll
        for (int c = 0; c < 4; c++) {
            atomicAdd(&s_sum[lane16 * 4 + c], ls[c]);
            atomicAdd(&s_sq[lane16 * 4 + c], lq[c]);
        }
    }
    __syncthreads();
    if (tid < HDIM) {
        atomicAdd(&g_stats[layer][tid], s_sum[tid]);
        atomicAdd(&g_stats[layer][HDIM + tid], s_sq[tid]);
    }
}

// ---------------------------------------------------------------------------
// classifier with in-block final BN+ReLU: out = relu(bn(agg) @ W1 + b1) @ W2 + b2
__global__ void k_classifier(const float* __restrict__ W1,
                             const float* __restrict__ b1,
                             const float* __restrict__ W2,
                             const float* __restrict__ b2,
                             const float* __restrict__ gamma,
                             const float* __restrict__ beta,
                             float* __restrict__ out, int n) {
    __shared__ float W1sm[HDIM * HC];
    __shared__ float s_sc[HDIM], s_sf[HDIM];
    int tid = threadIdx.x;
    if (tid < HDIM) {
        float inv_n = 1.0f / (float)n;
        float mean = g_stats[NLAYERS - 1][tid] * inv_n;
        float var = g_stats[NLAYERS - 1][HDIM + tid] * inv_n - mean * mean;
        float inv = rsqrtf(var + BN_EPS);
        float sc = gamma[tid] * inv;
        s_sc[tid] = sc;
        s_sf[tid] = beta[tid] - mean * sc;
    }
#pragma unroll
    for (int i = tid; i < HDIM * HC; i += 256) W1sm[i] = W1[i];
    __syncthreads();

    int lane = tid & 31;
    int warp = tid >> 5;
    float b1v = b1[lane];
    float w2v = W2[lane];
    float b2v = b2[0];
    float sc0 = s_sc[lane],      sf0 = s_sf[lane];
    float sc1 = s_sc[lane + 32], sf1 = s_sf[lane + 32];
    int base = blockIdx.x * 64 + warp * 8;

    for (int i = 0; i < 8; i++) {
        int node = base + i;
        if (node >= n) break;
        float h0 = fmaxf(fmaf(g_agg[node * HDIM + lane],      sc0, sf0), 0.f);
        float h1 = fmaxf(fmaf(g_agg[node * HDIM + 32 + lane], sc1, sf1), 0.f);
        float acc = b1v;
#pragma unroll
        for (int k = 0; k < 32; k++)
            acc = fmaf(__shfl_sync(0xFFFFFFFFu, h0, k), W1sm[k * HC + lane], acc);
#pragma unroll
        for (int k = 0; k < 32; k++)
            acc = fmaf(__shfl_sync(0xFFFFFFFFu, h1, k), W1sm[(k + 32) * HC + lane], acc);
        float r = fmaxf(acc, 0.0f) * w2v;
#pragma unroll
        for (int off = 16; off > 0; off >>= 1)
            r += __shfl_xor_sync(0xFFFFFFFFu, r, off);
        if (lane == 0) out[node] = r + b2v;
    }
}

// ---------------------------------------------------------------------------
extern "C" void kernel_launch(void* const* d_in, const int* in_sizes, int n_in,
                              void* d_out, int out_size) {
    const float* x        = (const float*)d_in[0];
    const int*   ei       = (const int*)d_in[1];
    const float* W_in     = (const float*)d_in[2];
    const float* b_in     = (const float*)d_in[3];
    const float* conv_W   = (const float*)d_in[4];
    // d_in[5] = conv_b : cancels exactly inside BatchNorm -> unused
    const float* bn_gamma = (const float*)d_in[6];
    const float* bn_beta  = (const float*)d_in[7];
    const float* W1       = (const float*)d_in[8];
    const float* b1       = (const float*)d_in[9];
    const float* W2       = (const float*)d_in[10];
    const float* b2       = (const float*)d_in[11];
    float* out = (float*)d_out;

    int n = in_sizes[0] / 5;
    int e = in_sizes[1] / 2;
    int nb = (n + SCAN_BLK - 1) / SCAN_BLK;

    k_count_deg<<<(e + 255) / 256, 256>>>(ei + e, e);
    k_scan_fused<<<nb, 256>>>(n, e);
    k_bucket<<<(e + 255) / 256, 256>>>(ei, e, n);

    int gemm_blocks = (n + GROWS - 1) / GROWS;
    int agg_blocks = (n + AGG_WARPS * NODES_PER_WARP - 1) / (AGG_WARPS * NODES_PER_WARP);

    for (int l = 0; l < NLAYERS; l++) {
        k_gemm_mma<<<gemm_blocks, 256>>>(
            conv_W + l * HDIM * HDIM, n, l, x, W_in, b_in,
            l > 0 ? bn_gamma + (l - 1) * HDIM : nullptr,
            l > 0 ? bn_beta + (l - 1) * HDIM : nullptr);
        k_aggregate<<<agg_blocks, 256>>>(n, l);
    }

    k_classifier<<<(n + 63) / 64, 256>>>(
        W1, b1, W2, b2,
        bn_gamma + (NLAYERS - 1) * HDIM, bn_beta + (NLAYERS - 1) * HDIM, out, n);
}

// round 7
// speedup vs baseline: 1.0395x; 1.0395x over previous
#include <cuda_runtime.h>
#include <cuda_fp16.h>

#define NMAX 100000
#define EMAX 1600000
#define HDIM 64
#define HC 32
#define NLAYERS 3
#define BN_EPS 1e-5f
#define SCAN_BLK 1024
#define SCAN_MAXB 128

// ---- scratch (device globals; no allocation allowed) ----
__device__ __half2 g_hs2[NMAX * 32];       // (h @ W) * dinv[row], fp16 pairs
__device__ float g_agg[NMAX * HDIM];       // pre-BN aggregated features (fp32)
__device__ int   g_cnt [NMAX];             // in-degree counts (left at 0 on exit)
__device__ float g_dinv[NMAX];             // (deg+1)^-1/2
__device__ int   g_row [NMAX + 1];         // CSR row pointers (by dst)
__device__ int   g_cur [NMAX];             // bucket cursors
__device__ int   g_srcs[EMAX];             // src node ids sorted by dst
__device__ volatile int g_part[SCAN_MAXB]; // lookback partials (total+1)
__device__ float g_stats[NLAYERS][2 * HDIM]; // per-layer channel sum, sumsq

static __device__ __forceinline__ unsigned s2u(const void* p) {
    return (unsigned)__cvta_generic_to_shared(p);
}

// ---------------------------------------------------------------------------
// count in-degrees; block 0 also zeroes lookback partials + BN stats
__global__ void k_count_deg(const int* __restrict__ dst, int e) {
    int i = blockIdx.x * blockDim.x + threadIdx.x;
    if (blockIdx.x == 0) {
        if (threadIdx.x < SCAN_MAXB) *(int*)&g_part[threadIdx.x] = 0;
        for (int j = threadIdx.x; j < NLAYERS * 2 * HDIM; j += 256)
            (&g_stats[0][0])[j] = 0.0f;
    }
    if (i < e) atomicAdd(&g_cnt[dst[i]], 1);
}

// fused scan: dinv + exclusive prefix (decoupled lookback) -> g_row, g_cur
__global__ void k_scan_fused(int n, int e) {
    __shared__ int sh[256];
    int tid = threadIdx.x, b = blockIdx.x;
    int base = b * SCAN_BLK + tid * 4;

    int v[4]; int mine = 0;
    if (base + 4 <= n) {
        int4 c = *reinterpret_cast<const int4*>(&g_cnt[base]);
        v[0] = c.x; v[1] = c.y; v[2] = c.z; v[3] = c.w;
        g_dinv[base + 0] = rsqrtf((float)c.x + 1.0f);
        g_dinv[base + 1] = rsqrtf((float)c.y + 1.0f);
        g_dinv[base + 2] = rsqrtf((float)c.z + 1.0f);
        g_dinv[base + 3] = rsqrtf((float)c.w + 1.0f);
        mine = c.x + c.y + c.z + c.w;
    } else {
#pragma unroll
        for (int k = 0; k < 4; k++) {
            v[k] = 0;
            if (base + k < n) {
                int c = g_cnt[base + k];
                v[k] = c;
                g_dinv[base + k] = rsqrtf((float)c + 1.0f);
                mine += c;
            }
        }
    }

    sh[tid] = mine;
    __syncthreads();
    for (int o = 1; o < 256; o <<= 1) {
        int t = (tid >= o) ? sh[tid - o] : 0;
        __syncthreads();
        sh[tid] += t;
        __syncthreads();
    }
    int excl = sh[tid] - mine;
    int total = sh[255];

    if (tid == 0) atomicExch((int*)&g_part[b], total + 1);
    int pref = 0;
    for (int i = tid; i < b; i += 256) {
        int p;
        while ((p = g_part[i]) == 0) {}
        pref += p - 1;
    }
    __syncthreads();
    sh[tid] = pref;
    __syncthreads();
    for (int o = 128; o > 0; o >>= 1) {
        if (tid < o) sh[tid] += sh[tid + o];
        __syncthreads();
    }
    int off = sh[0] + excl;

#pragma unroll
    for (int k = 0; k < 4; k++) {
        int idx = base + k;
        if (idx < n) {
            g_row[idx] = off;
            g_cur[idx] = off;
            off += v[k];
        }
    }
    if (b == 0 && tid == 0) g_row[n] = e;
}

// counting-sort bucket placement; also re-zero g_cnt for the next replay
__global__ void k_bucket(const int* __restrict__ ei, int e, int n) {
    int i = blockIdx.x * blockDim.x + threadIdx.x;
    if (i < n) g_cnt[i] = 0;
    if (i >= e) return;
    int s = ei[i];
    int d = ei[e + i];
    int pos = atomicAdd(&g_cur[d], 1);
    g_srcs[pos] = s;
}

// ---------------------------------------------------------------------------
// Tensor-core GEMM: 128 nodes x 64 cols per block, 8 warps (16 rows each).
// Two-half structure: 4 nt-tiles per half, epilogue after each half.
#define GROWS 128
#define ASTRIDE 72   // halves; 144B rows: 16B aligned, ldmatrix conflict-free
__global__ void __launch_bounds__(256, 1) k_gemm_mma(
    const float* __restrict__ W, int n, int layer,
    const float* __restrict__ x, const float* __restrict__ Win,
    const float* __restrict__ bin,
    const float* __restrict__ gamma, const float* __restrict__ beta) {
    __shared__ __half Asm[GROWS * ASTRIDE];
    __shared__ __half Wsm[HDIM * ASTRIDE];
    __shared__ float s_sc[HDIM], s_sf[HDIM];

    int tid = threadIdx.x;
    int node0 = blockIdx.x * GROWS;

    if (layer > 0) {
        if (tid < HDIM) {
            float inv_n = 1.0f / (float)n;
            float mean = g_stats[layer - 1][tid] * inv_n;
            float var = g_stats[layer - 1][HDIM + tid] * inv_n - mean * mean;
            float inv = rsqrtf(var + BN_EPS);
            float sc = gamma[tid] * inv;
            s_sc[tid] = sc;
            s_sf[tid] = beta[tid] - mean * sc;
        }
        __syncthreads();
    }

    // W (64x64 fp32) -> fp16 smem
    for (int i = tid; i < HDIM * HDIM / 4; i += 256) {
        float4 w = *reinterpret_cast<const float4*>(&W[i * 4]);
        int r = i >> 4;
        int c = (i * 4) & 63;
        __half2 h0 = __floats2half2_rn(w.x, w.y);
        __half2 h1 = __floats2half2_rn(w.z, w.w);
        uint2 pk;
        pk.x = *reinterpret_cast<unsigned*>(&h0);
        pk.y = *reinterpret_cast<unsigned*>(&h1);
        *reinterpret_cast<uint2*>(&Wsm[r * ASTRIDE + c]) = pk;
    }

    // A tile (128 x 64) -> fp16 smem, fused BN/relu or input-proj
#pragma unroll
    for (int it = 0; it < 8; it++) {
        int idx = tid + it * 256;
        int row = idx >> 4;
        int c4 = (idx & 15) * 4;
        int node = node0 + row;
        float4 v = make_float4(0.f, 0.f, 0.f, 0.f);
        if (node < n) {
            if (layer > 0) {
                v = *reinterpret_cast<const float4*>(&g_agg[node * HDIM + c4]);
                v.x = fmaf(v.x, s_sc[c4 + 0], s_sf[c4 + 0]);
                v.y = fmaf(v.y, s_sc[c4 + 1], s_sf[c4 + 1]);
                v.z = fmaf(v.z, s_sc[c4 + 2], s_sf[c4 + 2]);
                v.w = fmaf(v.w, s_sc[c4 + 3], s_sf[c4 + 3]);
            } else {
                v = *reinterpret_cast<const float4*>(&bin[c4]);
#pragma unroll
                for (int k = 0; k < 5; k++) {
                    float xv = __ldg(&x[node * 5 + k]);
                    float4 w = *reinterpret_cast<const float4*>(&Win[k * HDIM + c4]);
                    v.x = fmaf(xv, w.x, v.x);
                    v.y = fmaf(xv, w.y, v.y);
                    v.z = fmaf(xv, w.z, v.z);
                    v.w = fmaf(xv, w.w, v.w);
                }
            }
            v.x = fmaxf(v.x, 0.f); v.y = fmaxf(v.y, 0.f);
            v.z = fmaxf(v.z, 0.f); v.w = fmaxf(v.w, 0.f);
        }
        __half2 h0 = __floats2half2_rn(v.x, v.y);
        __half2 h1 = __floats2half2_rn(v.z, v.w);
        uint2 pk;
        pk.x = *reinterpret_cast<unsigned*>(&h0);
        pk.y = *reinterpret_cast<unsigned*>(&h1);
        *reinterpret_cast<uint2*>(&Asm[row * ASTRIDE + c4]) = pk;
    }
    __syncthreads();

    int warp = tid >> 5, lane = tid & 31;
    int wrow = warp * 16;
    int r15 = lane & 15;
    int cb8 = (lane >> 4) << 3;

    // A fragments for all 4 k-steps (m16k16 each): 16 regs
    unsigned a[4][4];
#pragma unroll
    for (int ks = 0; ks < 4; ks++) {
        unsigned addr = s2u(&Asm[(wrow + r15) * ASTRIDE + ks * 16 + cb8]);
        asm volatile("ldmatrix.sync.aligned.m8n8.x4.shared.b16 {%0,%1,%2,%3}, [%4];"
                     : "=r"(a[ks][0]), "=r"(a[ks][1]), "=r"(a[ks][2]), "=r"(a[ks][3])
                     : "r"(addr));
    }

    int gr = lane >> 2;
    int qp = lane & 3;
    int node_a = node0 + wrow + gr;
    int node_b = node_a + 8;
    float dia = (node_a < n) ? g_dinv[node_a] : 0.f;
    float dib = (node_b < n) ? g_dinv[node_b] : 0.f;

    // two halves of 4 nt-tiles each; epilogue per half
#pragma unroll
    for (int h = 0; h < 2; h++) {
        float acc[4][4];
#pragma unroll
        for (int t = 0; t < 4; t++)
#pragma unroll
            for (int q = 0; q < 4; q++) acc[t][q] = 0.0f;

#pragma unroll
        for (int p = 0; p < 2; p++) {          // nt pair within half
#pragma unroll
            for (int ks = 0; ks < 4; ks++) {
                unsigned b0, b1, b2, b3;
                unsigned baddr = s2u(&Wsm[(ks * 16 + r15) * ASTRIDE +
                                          h * 32 + p * 16 + cb8]);
                asm volatile("ldmatrix.sync.aligned.m8n8.x4.trans.shared.b16 {%0,%1,%2,%3}, [%4];"
                             : "=r"(b0), "=r"(b1), "=r"(b2), "=r"(b3) : "r"(baddr));
                asm volatile(
                    "mma.sync.aligned.m16n8k16.row.col.f32.f16.f16.f32 "
                    "{%0,%1,%2,%3}, {%4,%5,%6,%7}, {%8,%9}, {%0,%1,%2,%3};"
                    : "+f"(acc[2 * p][0]), "+f"(acc[2 * p][1]),
                      "+f"(acc[2 * p][2]), "+f"(acc[2 * p][3])
                    : "r"(a[ks][0]), "r"(a[ks][1]), "r"(a[ks][2]), "r"(a[ks][3]),
                      "r"(b0), "r"(b1));
                asm volatile(
                    "mma.sync.aligned.m16n8k16.row.col.f32.f16.f16.f32 "
                    "{%0,%1,%2,%3}, {%4,%5,%6,%7}, {%8,%9}, {%0,%1,%2,%3};"
                    : "+f"(acc[2 * p + 1][0]), "+f"(acc[2 * p + 1][1]),
                      "+f"(acc[2 * p + 1][2]), "+f"(acc[2 * p + 1][3])
                    : "r"(a[ks][0]), "r"(a[ks][1]), "r"(a[ks][2]), "r"(a[ks][3]),
                      "r"(b2), "r"(b3));
            }
        }

#pragma unroll
        for (int t = 0; t < 4; t++) {
            int nt = h * 4 + t;
            if (node_a < n)
                g_hs2[node_a * 32 + nt * 4 + qp] =
                    __floats2half2_rn(acc[t][0] * dia, acc[t][1] * dia);
            if (node_b < n)
                g_hs2[node_b * 32 + nt * 4 + qp] =
                    __floats2half2_rn(acc[t][2] * dib, acc[t][3] * dib);
        }
    }
}

// ---------------------------------------------------------------------------
// pull-based aggregation + BN stats (R5 version: lane owns channel pair)
#define AGG_WARPS 8
#define NODES_PER_WARP 8
__global__ void k_aggregate(int n, int layer) {
    __shared__ float s_sum[HDIM], s_sq[HDIM];
    int tid = threadIdx.x, lane = tid & 31, warp = tid >> 5;
    if (tid < HDIM) { s_sum[tid] = 0.f; s_sq[tid] = 0.f; }
    __syncthreads();

    float ls0 = 0.f, lq0 = 0.f, ls1 = 0.f, lq1 = 0.f;
    int node0 = (blockIdx.x * AGG_WARPS + warp) * NODES_PER_WARP;

    for (int i = 0; i < NODES_PER_WARP; i++) {
        int node = node0 + i;
        if (node >= n) break;
        int beg = g_row[node], end = g_row[node + 1];
        float a0 = 0.f, a1 = 0.f;
        int j = beg;
        for (; j + 8 <= end; j += 8) {
            int ss[8];
#pragma unroll
            for (int u = 0; u < 8; u++) ss[u] = g_srcs[j + u];
            float2 f[8];
#pragma unroll
            for (int u = 0; u < 8; u++)
                f[u] = __half22float2(g_hs2[ss[u] * 32 + lane]);
#pragma unroll
            for (int u = 0; u < 8; u++) { a0 += f[u].x; a1 += f[u].y; }
        }
        for (; j < end; j++) {
            float2 f = __half22float2(g_hs2[g_srcs[j] * 32 + lane]);
            a0 += f.x; a1 += f.y;
        }
        float2 self = __half22float2(g_hs2[node * 32 + lane]);
        float di = g_dinv[node];
        a0 = (a0 + self.x) * di;
        a1 = (a1 + self.y) * di;
        float2 o; o.x = a0; o.y = a1;
        *reinterpret_cast<float2*>(&g_agg[node * HDIM + 2 * lane]) = o;
        ls0 += a0; lq0 = fmaf(a0, a0, lq0);
        ls1 += a1; lq1 = fmaf(a1, a1, lq1);
    }

    atomicAdd(&s_sum[2 * lane], ls0);
    atomicAdd(&s_sq[2 * lane], lq0);
    atomicAdd(&s_sum[2 * lane + 1], ls1);
    atomicAdd(&s_sq[2 * lane + 1], lq1);
    __syncthreads();
    if (tid < HDIM) {
        atomicAdd(&g_stats[layer][tid], s_sum[tid]);
        atomicAdd(&g_stats[layer][HDIM + tid], s_sq[tid]);
    }
}

// ---------------------------------------------------------------------------
// classifier with in-block final BN+ReLU: out = relu(bn(agg) @ W1 + b1) @ W2 + b2
__global__ void k_classifier(const float* __restrict__ W1,
                             const float* __restrict__ b1,
                             const float* __restrict__ W2,
                             const float* __restrict__ b2,
                             const float* __restrict__ gamma,
                             const float* __restrict__ beta,
                             float* __restrict__ out, int n) {
    __shared__ float W1sm[HDIM * HC];
    __shared__ float s_sc[HDIM], s_sf[HDIM];
    int tid = threadIdx.x;
    if (tid < HDIM) {
        float inv_n = 1.0f / (float)n;
        float mean = g_stats[NLAYERS - 1][tid] * inv_n;
        float var = g_stats[NLAYERS - 1][HDIM + tid] * inv_n - mean * mean;
        float inv = rsqrtf(var + BN_EPS);
        float sc = gamma[tid] * inv;
        s_sc[tid] = sc;
        s_sf[tid] = beta[tid] - mean * sc;
    }
#pragma unroll
    for (int i = tid; i < HDIM * HC; i += 256) W1sm[i] = W1[i];
    __syncthreads();

    int lane = tid & 31;
    int warp = tid >> 5;
    float b1v = b1[lane];
    float w2v = W2[lane];
    float b2v = b2[0];
    float sc0 = s_sc[lane],      sf0 = s_sf[lane];
    float sc1 = s_sc[lane + 32], sf1 = s_sf[lane + 32];
    int base = blockIdx.x * 64 + warp * 8;

    for (int i = 0; i < 8; i++) {
        int node = base + i;
        if (node >= n) break;
        float h0 = fmaxf(fmaf(g_agg[node * HDIM + lane],      sc0, sf0), 0.f);
        float h1 = fmaxf(fmaf(g_agg[node * HDIM + 32 + lane], sc1, sf1), 0.f);
        float acc = b1v;
#pragma unroll
        for (int k = 0; k < 32; k++)
            acc = fmaf(__shfl_sync(0xFFFFFFFFu, h0, k), W1sm[k * HC + lane], acc);
#pragma unroll
        for (int k = 0; k < 32; k++)
            acc = fmaf(__shfl_sync(0xFFFFFFFFu, h1, k), W1sm[(k + 32) * HC + lane], acc);
        float r = fmaxf(acc, 0.0f) * w2v;
#pragma unroll
        for (int off = 16; off > 0; off >>= 1)
            r += __shfl_xor_sync(0xFFFFFFFFu, r, off);
        if (lane == 0) out[node] = r + b2v;
    }
}

// ---------------------------------------------------------------------------
extern "C" void kernel_launch(void* const* d_in, const int* in_sizes, int n_in,
                              void* d_out, int out_size) {
    const float* x        = (const float*)d_in[0];
    const int*   ei       = (const int*)d_in[1];
    const float* W_in     = (const float*)d_in[2];
    const float* b_in     = (const float*)d_in[3];
    const float* conv_W   = (const float*)d_in[4];
    // d_in[5] = conv_b : cancels exactly inside BatchNorm -> unused
    const float* bn_gamma = (const float*)d_in[6];
    const float* bn_beta  = (const float*)d_in[7];
    const float* W1       = (const float*)d_in[8];
    const float* b1       = (const float*)d_in[9];
    const float* W2       = (const float*)d_in[10];
    const float* b2       = (const float*)d_in[11];
    float* out = (float*)d_out;

    int n = in_sizes[0] / 5;
    int e = in_sizes[1] / 2;
    int nb = (n + SCAN_BLK - 1) / SCAN_BLK;

    k_count_deg<<<(e + 255) / 256, 256>>>(ei + e, e);
    k_scan_fused<<<nb, 256>>>(n, e);
    k_bucket<<<(e + 255) / 256, 256>>>(ei, e, n);

    int gemm_blocks = (n + GROWS - 1) / GROWS;
    int agg_blocks = (n + AGG_WARPS * NODES_PER_WARP - 1) / (AGG_WARPS * NODES_PER_WARP);

    for (int l = 0; l < NLAYERS; l++) {
        k_gemm_mma<<<gemm_blocks, 256>>>(
            conv_W + l * HDIM * HDIM, n, l, x, W_in, b_in,
            l > 0 ? bn_gamma + (l - 1) * HDIM : nullptr,
            l > 0 ? bn_beta + (l - 1) * HDIM : nullptr);
        k_aggregate<<<agg_blocks, 256>>>(n, l);
    }

    k_classifier<<<(n + 63) / 64, 256>>>(
        W1, b1, W2, b2,
        bn_gamma + (NLAYERS - 1) * HDIM, bn_beta + (NLAYERS - 1) * HDIM, out, n);
}

// round 8
// speedup vs baseline: 1.0636x; 1.0232x over previous
#include <cuda_runtime.h>
#include <cuda_fp16.h>

#define NMAX 100000
#define EMAX 1600000
#define HDIM 64
#define HC 32
#define NLAYERS 3
#define BN_EPS 1e-5f
#define SCAN_BLK 1024
#define SCAN_MAXB 128

// ---- scratch (device globals; no allocation allowed) ----
__device__ __half2 g_hs2[NMAX * 32];       // (h @ W) * dinv[row], fp16 pairs
__device__ float g_agg[NMAX * HDIM];       // pre-BN aggregated features (fp32)
__device__ int   g_cnt [NMAX];             // in-degree counts (left at 0 on exit)
__device__ float g_dinv[NMAX];             // (deg+1)^-1/2
__device__ int   g_row [NMAX + 1];         // CSR row pointers (by dst)
__device__ int   g_cur [NMAX];             // bucket cursors
__device__ int   g_srcs[EMAX];             // src node ids sorted by dst
__device__ volatile int g_part[SCAN_MAXB]; // lookback partials (total+1)
__device__ float g_stats[NLAYERS][2 * HDIM]; // per-layer channel sum, sumsq
__device__ __half g_w16[NLAYERS][HDIM * HDIM]; // conv weights pre-converted fp16

static __device__ __forceinline__ unsigned s2u(const void* p) {
    return (unsigned)__cvta_generic_to_shared(p);
}

// ---------------------------------------------------------------------------
// count in-degrees; block 0 zeroes lookback partials + BN stats;
// blocks 1..NLAYERS convert conv_W[layer] to fp16 (same values the GEMM
// converted per-block before -> identical numerics).
__global__ void k_count_deg(const int* __restrict__ dst, int e,
                            const float* __restrict__ conv_W) {
    int i = blockIdx.x * blockDim.x + threadIdx.x;
    if (blockIdx.x == 0) {
        if (threadIdx.x < SCAN_MAXB) *(int*)&g_part[threadIdx.x] = 0;
        for (int j = threadIdx.x; j < NLAYERS * 2 * HDIM; j += 256)
            (&g_stats[0][0])[j] = 0.0f;
    } else if (blockIdx.x <= NLAYERS) {
        int l = blockIdx.x - 1;
        const float* W = conv_W + l * HDIM * HDIM;
        for (int j = threadIdx.x; j < HDIM * HDIM / 4; j += 256) {
            float4 w = *reinterpret_cast<const float4*>(&W[j * 4]);
            __half2 h0 = __floats2half2_rn(w.x, w.y);
            __half2 h1 = __floats2half2_rn(w.z, w.w);
            uint2 pk;
            pk.x = *reinterpret_cast<unsigned*>(&h0);
            pk.y = *reinterpret_cast<unsigned*>(&h1);
            *reinterpret_cast<uint2*>(&g_w16[l][j * 4]) = pk;
        }
    }
    if (i < e) atomicAdd(&g_cnt[dst[i]], 1);
}

// fused scan: dinv + exclusive prefix (decoupled lookback) -> g_row, g_cur
__global__ void k_scan_fused(int n, int e) {
    __shared__ int sh[256];
    int tid = threadIdx.x, b = blockIdx.x;
    int base = b * SCAN_BLK + tid * 4;

    int v[4]; int mine = 0;
    if (base + 4 <= n) {
        int4 c = *reinterpret_cast<const int4*>(&g_cnt[base]);
        v[0] = c.x; v[1] = c.y; v[2] = c.z; v[3] = c.w;
        g_dinv[base + 0] = rsqrtf((float)c.x + 1.0f);
        g_dinv[base + 1] = rsqrtf((float)c.y + 1.0f);
        g_dinv[base + 2] = rsqrtf((float)c.z + 1.0f);
        g_dinv[base + 3] = rsqrtf((float)c.w + 1.0f);
        mine = c.x + c.y + c.z + c.w;
    } else {
#pragma unroll
        for (int k = 0; k < 4; k++) {
            v[k] = 0;
            if (base + k < n) {
                int c = g_cnt[base + k];
                v[k] = c;
                g_dinv[base + k] = rsqrtf((float)c + 1.0f);
                mine += c;
            }
        }
    }

    sh[tid] = mine;
    __syncthreads();
    for (int o = 1; o < 256; o <<= 1) {
        int t = (tid >= o) ? sh[tid - o] : 0;
        __syncthreads();
        sh[tid] += t;
        __syncthreads();
    }
    int excl = sh[tid] - mine;
    int total = sh[255];

    if (tid == 0) atomicExch((int*)&g_part[b], total + 1);
    int pref = 0;
    for (int i = tid; i < b; i += 256) {
        int p;
        while ((p = g_part[i]) == 0) {}
        pref += p - 1;
    }
    __syncthreads();
    sh[tid] = pref;
    __syncthreads();
    for (int o = 128; o > 0; o >>= 1) {
        if (tid < o) sh[tid] += sh[tid + o];
        __syncthreads();
    }
    int off = sh[0] + excl;

#pragma unroll
    for (int k = 0; k < 4; k++) {
        int idx = base + k;
        if (idx < n) {
            g_row[idx] = off;
            g_cur[idx] = off;
            off += v[k];
        }
    }
    if (b == 0 && tid == 0) g_row[n] = e;
}

// counting-sort bucket placement; also re-zero g_cnt for the next replay
__global__ void k_bucket(const int* __restrict__ ei, int e, int n) {
    int i = blockIdx.x * blockDim.x + threadIdx.x;
    if (i < n) g_cnt[i] = 0;
    if (i >= e) return;
    int s = ei[i];
    int d = ei[e + i];
    int pos = atomicAdd(&g_cur[d], 1);
    g_srcs[pos] = s;
}

// ---------------------------------------------------------------------------
// Tensor-core GEMM (R5 structure): 128 nodes x 64 cols per block, 8 warps.
// W loaded pre-converted fp16 from g_w16.
#define GROWS 128
#define ASTRIDE 72   // halves; 144B rows: 16B aligned, ldmatrix conflict-free
__global__ void __launch_bounds__(256) k_gemm_mma(
    int n, int layer,
    const float* __restrict__ x, const float* __restrict__ Win,
    const float* __restrict__ bin,
    const float* __restrict__ gamma, const float* __restrict__ beta) {
    __shared__ __half Asm[GROWS * ASTRIDE];
    __shared__ __half Wsm[HDIM * ASTRIDE];
    __shared__ float s_sc[HDIM], s_sf[HDIM];

    int tid = threadIdx.x;
    int node0 = blockIdx.x * GROWS;

    if (layer > 0) {
        if (tid < HDIM) {
            float inv_n = 1.0f / (float)n;
            float mean = g_stats[layer - 1][tid] * inv_n;
            float var = g_stats[layer - 1][HDIM + tid] * inv_n - mean * mean;
            float inv = rsqrtf(var + BN_EPS);
            float sc = gamma[tid] * inv;
            s_sc[tid] = sc;
            s_sf[tid] = beta[tid] - mean * sc;
        }
        __syncthreads();
    }

    // W (64x64 fp16, pre-converted) -> smem, uint4 = 8 halves
    for (int i = tid; i < HDIM * HDIM / 8; i += 256) {
        uint4 w = *reinterpret_cast<const uint4*>(&g_w16[layer][i * 8]);
        int r = i >> 3;
        int c = (i * 8) & 63;
        *reinterpret_cast<uint4*>(&Wsm[r * ASTRIDE + c]) = w;
    }

    // A tile (128 x 64) -> fp16 smem, fused BN/relu or input-proj
#pragma unroll
    for (int it = 0; it < 8; it++) {
        int idx = tid + it * 256;
        int row = idx >> 4;
        int c4 = (idx & 15) * 4;
        int node = node0 + row;
        float4 v = make_float4(0.f, 0.f, 0.f, 0.f);
        if (node < n) {
            if (layer > 0) {
                v = *reinterpret_cast<const float4*>(&g_agg[node * HDIM + c4]);
                v.x = fmaf(v.x, s_sc[c4 + 0], s_sf[c4 + 0]);
                v.y = fmaf(v.y, s_sc[c4 + 1], s_sf[c4 + 1]);
                v.z = fmaf(v.z, s_sc[c4 + 2], s_sf[c4 + 2]);
                v.w = fmaf(v.w, s_sc[c4 + 3], s_sf[c4 + 3]);
            } else {
                v = *reinterpret_cast<const float4*>(&bin[c4]);
#pragma unroll
                for (int k = 0; k < 5; k++) {
                    float xv = __ldg(&x[node * 5 + k]);
                    float4 w = *reinterpret_cast<const float4*>(&Win[k * HDIM + c4]);
                    v.x = fmaf(xv, w.x, v.x);
                    v.y = fmaf(xv, w.y, v.y);
                    v.z = fmaf(xv, w.z, v.z);
                    v.w = fmaf(xv, w.w, v.w);
                }
            }
            v.x = fmaxf(v.x, 0.f); v.y = fmaxf(v.y, 0.f);
            v.z = fmaxf(v.z, 0.f); v.w = fmaxf(v.w, 0.f);
        }
        __half2 h0 = __floats2half2_rn(v.x, v.y);
        __half2 h1 = __floats2half2_rn(v.z, v.w);
        uint2 pk;
        pk.x = *reinterpret_cast<unsigned*>(&h0);
        pk.y = *reinterpret_cast<unsigned*>(&h1);
        *reinterpret_cast<uint2*>(&Asm[row * ASTRIDE + c4]) = pk;
    }
    __syncthreads();

    int warp = tid >> 5, lane = tid & 31;
    int wrow = warp * 16;

    // A fragments for all 4 k-steps (m16k16 each)
    unsigned a[4][4];
    {
        int r = lane & 15;
        int cb = (lane >> 4) << 3;
#pragma unroll
        for (int ks = 0; ks < 4; ks++) {
            unsigned addr = s2u(&Asm[(wrow + r) * ASTRIDE + ks * 16 + cb]);
            asm volatile("ldmatrix.sync.aligned.m8n8.x4.shared.b16 {%0,%1,%2,%3}, [%4];"
                         : "=r"(a[ks][0]), "=r"(a[ks][1]), "=r"(a[ks][2]), "=r"(a[ks][3])
                         : "r"(addr));
        }
    }

    float acc[8][4];
#pragma unroll
    for (int nt = 0; nt < 8; nt++)
#pragma unroll
        for (int q = 0; q < 4; q++) acc[nt][q] = 0.0f;

#pragma unroll
    for (int nt = 0; nt < 8; nt++) {
#pragma unroll
        for (int ks = 0; ks < 4; ks++) {
            unsigned b0, b1;
            int r = lane & 15;
            unsigned baddr = s2u(&Wsm[(ks * 16 + r) * ASTRIDE + nt * 8]);
            asm volatile("ldmatrix.sync.aligned.m8n8.x2.trans.shared.b16 {%0,%1}, [%2];"
                         : "=r"(b0), "=r"(b1) : "r"(baddr));
            asm volatile(
                "mma.sync.aligned.m16n8k16.row.col.f32.f16.f16.f32 "
                "{%0,%1,%2,%3}, {%4,%5,%6,%7}, {%8,%9}, {%0,%1,%2,%3};"
                : "+f"(acc[nt][0]), "+f"(acc[nt][1]), "+f"(acc[nt][2]), "+f"(acc[nt][3])
                : "r"(a[ks][0]), "r"(a[ks][1]), "r"(a[ks][2]), "r"(a[ks][3]),
                  "r"(b0), "r"(b1));
        }
    }

    // epilogue: scale by dinv, pack fp16, store
    int gr = lane >> 2;
    int qp = lane & 3;
    int node_a = node0 + wrow + gr;
    int node_b = node_a + 8;
    float dia = (node_a < n) ? g_dinv[node_a] : 0.f;
    float dib = (node_b < n) ? g_dinv[node_b] : 0.f;
#pragma unroll
    for (int nt = 0; nt < 8; nt++) {
        if (node_a < n)
            g_hs2[node_a * 32 + nt * 4 + qp] =
                __floats2half2_rn(acc[nt][0] * dia, acc[nt][1] * dia);
        if (node_b < n)
            g_hs2[node_b * 32 + nt * 4 + qp] =
                __floats2half2_rn(acc[nt][2] * dib, acc[nt][3] * dib);
    }
}

// ---------------------------------------------------------------------------
// pull-based aggregation + BN stats (R5 lane layout; 8/4/1 tail pyramid)
#define AGG_WARPS 8
#define NODES_PER_WARP 8
__global__ void k_aggregate(int n, int layer) {
    __shared__ float s_sum[HDIM], s_sq[HDIM];
    int tid = threadIdx.x, lane = tid & 31, warp = tid >> 5;
    if (tid < HDIM) { s_sum[tid] = 0.f; s_sq[tid] = 0.f; }
    __syncthreads();

    float ls0 = 0.f, lq0 = 0.f, ls1 = 0.f, lq1 = 0.f;
    int node0 = (blockIdx.x * AGG_WARPS + warp) * NODES_PER_WARP;

    for (int i = 0; i < NODES_PER_WARP; i++) {
        int node = node0 + i;
        if (node >= n) break;
        int beg = g_row[node], end = g_row[node + 1];
        float a0 = 0.f, a1 = 0.f;
        int j = beg;
        for (; j + 8 <= end; j += 8) {
            int ss[8];
#pragma unroll
            for (int u = 0; u < 8; u++) ss[u] = g_srcs[j + u];
            float2 f[8];
#pragma unroll
            for (int u = 0; u < 8; u++)
                f[u] = __half22float2(g_hs2[ss[u] * 32 + lane]);
#pragma unroll
            for (int u = 0; u < 8; u++) { a0 += f[u].x; a1 += f[u].y; }
        }
        if (j + 4 <= end) {
            int ss[4];
#pragma unroll
            for (int u = 0; u < 4; u++) ss[u] = g_srcs[j + u];
            float2 f[4];
#pragma unroll
            for (int u = 0; u < 4; u++)
                f[u] = __half22float2(g_hs2[ss[u] * 32 + lane]);
#pragma unroll
            for (int u = 0; u < 4; u++) { a0 += f[u].x; a1 += f[u].y; }
            j += 4;
        }
        for (; j < end; j++) {
            float2 f = __half22float2(g_hs2[g_srcs[j] * 32 + lane]);
            a0 += f.x; a1 += f.y;
        }
        float2 self = __half22float2(g_hs2[node * 32 + lane]);
        float di = g_dinv[node];
        a0 = (a0 + self.x) * di;
        a1 = (a1 + self.y) * di;
        float2 o; o.x = a0; o.y = a1;
        *reinterpret_cast<float2*>(&g_agg[node * HDIM + 2 * lane]) = o;
        ls0 += a0; lq0 = fmaf(a0, a0, lq0);
        ls1 += a1; lq1 = fmaf(a1, a1, lq1);
    }

    atomicAdd(&s_sum[2 * lane], ls0);
    atomicAdd(&s_sq[2 * lane], lq0);
    atomicAdd(&s_sum[2 * lane + 1], ls1);
    atomicAdd(&s_sq[2 * lane + 1], lq1);
    __syncthreads();
    if (tid < HDIM) {
        atomicAdd(&g_stats[layer][tid], s_sum[tid]);
        atomicAdd(&g_stats[layer][HDIM + tid], s_sq[tid]);
    }
}

// ---------------------------------------------------------------------------
// classifier with in-block final BN+ReLU: out = relu(bn(agg) @ W1 + b1) @ W2 + b2
__global__ void k_classifier(const float* __restrict__ W1,
                             const float* __restrict__ b1,
                             const float* __restrict__ W2,
                             const float* __restrict__ b2,
                             const float* __restrict__ gamma,
                             const float* __restrict__ beta,
                             float* __restrict__ out, int n) {
    __shared__ float W1sm[HDIM * HC];
    __shared__ float s_sc[HDIM], s_sf[HDIM];
    int tid = threadIdx.x;
    if (tid < HDIM) {
        float inv_n = 1.0f / (float)n;
        float mean = g_stats[NLAYERS - 1][tid] * inv_n;
        float var = g_stats[NLAYERS - 1][HDIM + tid] * inv_n - mean * mean;
        float inv = rsqrtf(var + BN_EPS);
        float sc = gamma[tid] * inv;
        s_sc[tid] = sc;
        s_sf[tid] = beta[tid] - mean * sc;
    }
#pragma unroll
    for (int i = tid; i < HDIM * HC; i += 256) W1sm[i] = W1[i];
    __syncthreads();

    int lane = tid & 31;
    int warp = tid >> 5;
    float b1v = b1[lane];
    float w2v = W2[lane];
    float b2v = b2[0];
    float sc0 = s_sc[lane],      sf0 = s_sf[lane];
    float sc1 = s_sc[lane + 32], sf1 = s_sf[lane + 32];
    int base = blockIdx.x * 64 + warp * 8;

    for (int i = 0; i < 8; i++) {
        int node = base + i;
        if (node >= n) break;
        float h0 = fmaxf(fmaf(g_agg[node * HDIM + lane],      sc0, sf0), 0.f);
        float h1 = fmaxf(fmaf(g_agg[node * HDIM + 32 + lane], sc1, sf1), 0.f);
        float acc = b1v;
#pragma unroll
        for (int k = 0; k < 32; k++)
            acc = fmaf(__shfl_sync(0xFFFFFFFFu, h0, k), W1sm[k * HC + lane], acc);
#pragma unroll
        for (int k = 0; k < 32; k++)
            acc = fmaf(__shfl_sync(0xFFFFFFFFu, h1, k), W1sm[(k + 32) * HC + lane], acc);
        float r = fmaxf(acc, 0.0f) * w2v;
#pragma unroll
        for (int off = 16; off > 0; off >>= 1)
            r += __shfl_xor_sync(0xFFFFFFFFu, r, off);
        if (lane == 0) out[node] = r + b2v;
    }
}

// ---------------------------------------------------------------------------
extern "C" void kernel_launch(void* const* d_in, const int* in_sizes, int n_in,
                              void* d_out, int out_size) {
    const float* x        = (const float*)d_in[0];
    const int*   ei       = (const int*)d_in[1];
    const float* W_in     = (const float*)d_in[2];
    const float* b_in     = (const float*)d_in[3];
    const float* conv_W   = (const float*)d_in[4];
    // d_in[5] = conv_b : cancels exactly inside BatchNorm -> unused
    const float* bn_gamma = (const float*)d_in[6];
    const float* bn_beta  = (const float*)d_in[7];
    const float* W1       = (const float*)d_in[8];
    const float* b1       = (const float*)d_in[9];
    const float* W2       = (const float*)d_in[10];
    const float* b2       = (const float*)d_in[11];
    float* out = (float*)d_out;

    int n = in_sizes[0] / 5;
    int e = in_sizes[1] / 2;
    int nb = (n + SCAN_BLK - 1) / SCAN_BLK;

    k_count_deg<<<(e + 255) / 256, 256>>>(ei + e, e, conv_W);
    k_scan_fused<<<nb, 256>>>(n, e);
    k_bucket<<<(e + 255) / 256, 256>>>(ei, e, n);

    int gemm_blocks = (n + GROWS - 1) / GROWS;
    int agg_blocks = (n + AGG_WARPS * NODES_PER_WARP - 1) / (AGG_WARPS * NODES_PER_WARP);

    for (int l = 0; l < NLAYERS; l++) {
        k_gemm_mma<<<gemm_blocks, 256>>>(
            n, l, x, W_in, b_in,
            l > 0 ? bn_gamma + (l - 1) * HDIM : nullptr,
            l > 0 ? bn_beta + (l - 1) * HDIM : nullptr);
        k_aggregate<<<agg_blocks, 256>>>(n, l);
    }

    k_classifier<<<(n + 63) / 64, 256>>>(
        W1, b1, W2, b2,
        bn_gamma + (NLAYERS - 1) * HDIM, bn_beta + (NLAYERS - 1) * HDIM, out, n);
}

// round 9
// speedup vs baseline: 1.0916x; 1.0263x over previous
#include <cuda_runtime.h>
#include <cuda_fp16.h>

#define NMAX 100000
#define EMAX 1600000
#define HDIM 64
#define HC 32
#define NLAYERS 3
#define BN_EPS 1e-5f
#define SCAN_BLK 1024
#define SCAN_MAXB 128

// ---- scratch (device globals; no allocation allowed) ----
__device__ __half2 g_hs2[NMAX * 32];       // (h @ W) * dinv[row], fp16 pairs
__device__ float g_agg[NMAX * HDIM];       // pre-BN aggregated features (fp32)
__device__ int   g_cnt [NMAX];             // in-degree counts (left at 0 on exit)
__device__ float g_dinv[NMAX];             // (deg+1)^-1/2
__device__ int   g_row [NMAX + 1];         // CSR row pointers (by dst)
__device__ int   g_rank[EMAX];             // per-edge rank within its dst bucket
__device__ int   g_srcs[EMAX];             // src node ids sorted by dst
__device__ volatile int g_part[SCAN_MAXB]; // lookback partials (total+1)
__device__ float g_stats[NLAYERS][2 * HDIM]; // per-layer channel sum, sumsq
__device__ __half g_w16[NLAYERS][HDIM * HDIM]; // conv weights pre-converted fp16

static __device__ __forceinline__ unsigned s2u(const void* p) {
    return (unsigned)__cvta_generic_to_shared(p);
}

// ---------------------------------------------------------------------------
// count in-degrees, record per-edge rank; block 0 zeroes partials + BN stats;
// blocks 1..NLAYERS convert conv_W[layer] to fp16 (identical values to the
// per-block conversion the GEMM used before).
__global__ void k_count_deg(const int* __restrict__ dst, int e,
                            const float* __restrict__ conv_W) {
    int i = blockIdx.x * blockDim.x + threadIdx.x;
    if (blockIdx.x == 0) {
        if (threadIdx.x < SCAN_MAXB) *(int*)&g_part[threadIdx.x] = 0;
        for (int j = threadIdx.x; j < NLAYERS * 2 * HDIM; j += 256)
            (&g_stats[0][0])[j] = 0.0f;
    } else if (blockIdx.x <= NLAYERS) {
        int l = blockIdx.x - 1;
        const float* W = conv_W + l * HDIM * HDIM;
        for (int j = threadIdx.x; j < HDIM * HDIM / 4; j += 256) {
            float4 w = *reinterpret_cast<const float4*>(&W[j * 4]);
            __half2 h0 = __floats2half2_rn(w.x, w.y);
            __half2 h1 = __floats2half2_rn(w.z, w.w);
            uint2 pk;
            pk.x = *reinterpret_cast<unsigned*>(&h0);
            pk.y = *reinterpret_cast<unsigned*>(&h1);
            *reinterpret_cast<uint2*>(&g_w16[l][j * 4]) = pk;
        }
    }
    if (i < e) g_rank[i] = atomicAdd(&g_cnt[dst[i]], 1);
}

// fused scan: dinv + exclusive prefix (decoupled lookback) -> g_row
__global__ void k_scan_fused(int n, int e) {
    __shared__ int sh[256];
    int tid = threadIdx.x, b = blockIdx.x;
    int base = b * SCAN_BLK + tid * 4;

    int v[4]; int mine = 0;
    if (base + 4 <= n) {
        int4 c = *reinterpret_cast<const int4*>(&g_cnt[base]);
        v[0] = c.x; v[1] = c.y; v[2] = c.z; v[3] = c.w;
        g_dinv[base + 0] = rsqrtf((float)c.x + 1.0f);
        g_dinv[base + 1] = rsqrtf((float)c.y + 1.0f);
        g_dinv[base + 2] = rsqrtf((float)c.z + 1.0f);
        g_dinv[base + 3] = rsqrtf((float)c.w + 1.0f);
        mine = c.x + c.y + c.z + c.w;
    } else {
#pragma unroll
        for (int k = 0; k < 4; k++) {
            v[k] = 0;
            if (base + k < n) {
                int c = g_cnt[base + k];
                v[k] = c;
                g_dinv[base + k] = rsqrtf((float)c + 1.0f);
                mine += c;
            }
        }
    }

    sh[tid] = mine;
    __syncthreads();
    for (int o = 1; o < 256; o <<= 1) {
        int t = (tid >= o) ? sh[tid - o] : 0;
        __syncthreads();
        sh[tid] += t;
        __syncthreads();
    }
    int excl = sh[tid] - mine;
    int total = sh[255];

    if (tid == 0) atomicExch((int*)&g_part[b], total + 1);
    int pref = 0;
    for (int i = tid; i < b; i += 256) {
        int p;
        while ((p = g_part[i]) == 0) {}
        pref += p - 1;
    }
    __syncthreads();
    sh[tid] = pref;
    __syncthreads();
    for (int o = 128; o > 0; o >>= 1) {
        if (tid < o) sh[tid] += sh[tid + o];
        __syncthreads();
    }
    int off = sh[0] + excl;

#pragma unroll
    for (int k = 0; k < 4; k++) {
        int idx = base + k;
        if (idx < n) {
            g_row[idx] = off;
            off += v[k];
        }
    }
    if (b == 0 && tid == 0) g_row[n] = e;
}

// bucket placement: pure store using precomputed rank; re-zero g_cnt
__global__ void k_bucket(const int* __restrict__ ei, int e, int n) {
    int i = blockIdx.x * blockDim.x + threadIdx.x;
    if (i < n) g_cnt[i] = 0;
    if (i >= e) return;
    int s = ei[i];
    int d = ei[e + i];
    g_srcs[g_row[d] + g_rank[i]] = s;
}

// ---------------------------------------------------------------------------
// Tensor-core GEMM: 256 nodes per block (2 sub-tiles of 128), 8 warps.
// Inner structure identical to R5 (acc[8][4], per-nt x2.trans B ldmatrix).
#define GROWS 256
#define ASTRIDE 72   // halves; 144B rows: 16B aligned, ldmatrix conflict-free
__global__ void __launch_bounds__(256) k_gemm_mma(
    int n, int layer,
    const float* __restrict__ x, const float* __restrict__ Win,
    const float* __restrict__ bin,
    const float* __restrict__ gamma, const float* __restrict__ beta) {
    __shared__ __half Asm[128 * ASTRIDE];
    __shared__ __half Wsm[HDIM * ASTRIDE];
    __shared__ float s_sc[HDIM], s_sf[HDIM];

    int tid = threadIdx.x;

    if (layer > 0) {
        if (tid < HDIM) {
            float inv_n = 1.0f / (float)n;
            float mean = g_stats[layer - 1][tid] * inv_n;
            float var = g_stats[layer - 1][HDIM + tid] * inv_n - mean * mean;
            float inv = rsqrtf(var + BN_EPS);
            float sc = gamma[tid] * inv;
            s_sc[tid] = sc;
            s_sf[tid] = beta[tid] - mean * sc;
        }
    }

    // W (64x64 fp16, pre-converted) -> smem, uint4 = 8 halves
    for (int i = tid; i < HDIM * HDIM / 8; i += 256) {
        uint4 w = *reinterpret_cast<const uint4*>(&g_w16[layer][i * 8]);
        int r = i >> 3;
        int c = (i * 8) & 63;
        *reinterpret_cast<uint4*>(&Wsm[r * ASTRIDE + c]) = w;
    }
    __syncthreads();

    int warp = tid >> 5, lane = tid & 31;
    int wrow = warp * 16;
    int r15 = lane & 15;
    int cb8 = (lane >> 4) << 3;
    int gr = lane >> 2;
    int qp = lane & 3;

    for (int sub = 0; sub < 2; sub++) {
        int node0 = blockIdx.x * GROWS + sub * 128;

        // A tile (128 x 64) -> fp16 smem, fused BN/relu or input-proj
#pragma unroll
        for (int it = 0; it < 8; it++) {
            int idx = tid + it * 256;
            int row = idx >> 4;
            int c4 = (idx & 15) * 4;
            int node = node0 + row;
            float4 v = make_float4(0.f, 0.f, 0.f, 0.f);
            if (node < n) {
                if (layer > 0) {
                    v = *reinterpret_cast<const float4*>(&g_agg[node * HDIM + c4]);
                    v.x = fmaf(v.x, s_sc[c4 + 0], s_sf[c4 + 0]);
                    v.y = fmaf(v.y, s_sc[c4 + 1], s_sf[c4 + 1]);
                    v.z = fmaf(v.z, s_sc[c4 + 2], s_sf[c4 + 2]);
                    v.w = fmaf(v.w, s_sc[c4 + 3], s_sf[c4 + 3]);
                } else {
                    v = *reinterpret_cast<const float4*>(&bin[c4]);
#pragma unroll
                    for (int k = 0; k < 5; k++) {
                        float xv = __ldg(&x[node * 5 + k]);
                        float4 w = *reinterpret_cast<const float4*>(&Win[k * HDIM + c4]);
                        v.x = fmaf(xv, w.x, v.x);
                        v.y = fmaf(xv, w.y, v.y);
                        v.z = fmaf(xv, w.z, v.z);
                        v.w = fmaf(xv, w.w, v.w);
                    }
                }
                v.x = fmaxf(v.x, 0.f); v.y = fmaxf(v.y, 0.f);
                v.z = fmaxf(v.z, 0.f); v.w = fmaxf(v.w, 0.f);
            }
            __half2 h0 = __floats2half2_rn(v.x, v.y);
            __half2 h1 = __floats2half2_rn(v.z, v.w);
            uint2 pk;
            pk.x = *reinterpret_cast<unsigned*>(&h0);
            pk.y = *reinterpret_cast<unsigned*>(&h1);
            *reinterpret_cast<uint2*>(&Asm[row * ASTRIDE + c4]) = pk;
        }
        __syncthreads();

        // A fragments for all 4 k-steps (m16k16 each)
        unsigned a[4][4];
#pragma unroll
        for (int ks = 0; ks < 4; ks++) {
            unsigned addr = s2u(&Asm[(wrow + r15) * ASTRIDE + ks * 16 + cb8]);
            asm volatile("ldmatrix.sync.aligned.m8n8.x4.shared.b16 {%0,%1,%2,%3}, [%4];"
                         : "=r"(a[ks][0]), "=r"(a[ks][1]), "=r"(a[ks][2]), "=r"(a[ks][3])
                         : "r"(addr));
        }

        float acc[8][4];
#pragma unroll
        for (int nt = 0; nt < 8; nt++)
#pragma unroll
            for (int q = 0; q < 4; q++) acc[nt][q] = 0.0f;

#pragma unroll
        for (int nt = 0; nt < 8; nt++) {
#pragma unroll
            for (int ks = 0; ks < 4; ks++) {
                unsigned b0, b1;
                unsigned baddr = s2u(&Wsm[(ks * 16 + r15) * ASTRIDE + nt * 8]);
                asm volatile("ldmatrix.sync.aligned.m8n8.x2.trans.shared.b16 {%0,%1}, [%2];"
                             : "=r"(b0), "=r"(b1) : "r"(baddr));
                asm volatile(
                    "mma.sync.aligned.m16n8k16.row.col.f32.f16.f16.f32 "
                    "{%0,%1,%2,%3}, {%4,%5,%6,%7}, {%8,%9}, {%0,%1,%2,%3};"
                    : "+f"(acc[nt][0]), "+f"(acc[nt][1]), "+f"(acc[nt][2]), "+f"(acc[nt][3])
                    : "r"(a[ks][0]), "r"(a[ks][1]), "r"(a[ks][2]), "r"(a[ks][3]),
                      "r"(b0), "r"(b1));
            }
        }

        // epilogue: scale by dinv, pack fp16, store
        int node_a = node0 + wrow + gr;
        int node_b = node_a + 8;
        float dia = (node_a < n) ? g_dinv[node_a] : 0.f;
        float dib = (node_b < n) ? g_dinv[node_b] : 0.f;
#pragma unroll
        for (int nt = 0; nt < 8; nt++) {
            if (node_a < n)
                g_hs2[node_a * 32 + nt * 4 + qp] =
                    __floats2half2_rn(acc[nt][0] * dia, acc[nt][1] * dia);
            if (node_b < n)
                g_hs2[node_b * 32 + nt * 4 + qp] =
                    __floats2half2_rn(acc[nt][2] * dib, acc[nt][3] * dib);
        }
        __syncthreads();   // Asm reused next sub-tile
    }
}

// ---------------------------------------------------------------------------
// pull-based aggregation + BN stats (exact R5 loop: 8-unroll + singles tail)
#define AGG_WARPS 8
#define NODES_PER_WARP 8
__global__ void k_aggregate(int n, int layer) {
    __shared__ float s_sum[HDIM], s_sq[HDIM];
    int tid = threadIdx.x, lane = tid & 31, warp = tid >> 5;
    if (tid < HDIM) { s_sum[tid] = 0.f; s_sq[tid] = 0.f; }
    __syncthreads();

    float ls0 = 0.f, lq0 = 0.f, ls1 = 0.f, lq1 = 0.f;
    int node0 = (blockIdx.x * AGG_WARPS + warp) * NODES_PER_WARP;

    for (int i = 0; i < NODES_PER_WARP; i++) {
        int node = node0 + i;
        if (node >= n) break;
        int beg = g_row[node], end = g_row[node + 1];
        float a0 = 0.f, a1 = 0.f;
        int j = beg;
        for (; j + 8 <= end; j += 8) {
            int ss[8];
#pragma unroll
            for (int u = 0; u < 8; u++) ss[u] = g_srcs[j + u];
            float2 f[8];
#pragma unroll
            for (int u = 0; u < 8; u++)
                f[u] = __half22float2(g_hs2[ss[u] * 32 + lane]);
#pragma unroll
            for (int u = 0; u < 8; u++) { a0 += f[u].x; a1 += f[u].y; }
        }
        for (; j < end; j++) {
            float2 f = __half22float2(g_hs2[g_srcs[j] * 32 + lane]);
            a0 += f.x; a1 += f.y;
        }
        float2 self = __half22float2(g_hs2[node * 32 + lane]);
        float di = g_dinv[node];
        a0 = (a0 + self.x) * di;
        a1 = (a1 + self.y) * di;
        float2 o; o.x = a0; o.y = a1;
        *reinterpret_cast<float2*>(&g_agg[node * HDIM + 2 * lane]) = o;
        ls0 += a0; lq0 = fmaf(a0, a0, lq0);
        ls1 += a1; lq1 = fmaf(a1, a1, lq1);
    }

    atomicAdd(&s_sum[2 * lane], ls0);
    atomicAdd(&s_sq[2 * lane], lq0);
    atomicAdd(&s_sum[2 * lane + 1], ls1);
    atomicAdd(&s_sq[2 * lane + 1], lq1);
    __syncthreads();
    if (tid < HDIM) {
        atomicAdd(&g_stats[layer][tid], s_sum[tid]);
        atomicAdd(&g_stats[layer][HDIM + tid], s_sq[tid]);
    }
}

// ---------------------------------------------------------------------------
// classifier with in-block final BN+ReLU: out = relu(bn(agg) @ W1 + b1) @ W2 + b2
__global__ void k_classifier(const float* __restrict__ W1,
                             const float* __restrict__ b1,
                             const float* __restrict__ W2,
                             const float* __restrict__ b2,
                             const float* __restrict__ gamma,
                             const float* __restrict__ beta,
                             float* __restrict__ out, int n) {
    __shared__ float W1sm[HDIM * HC];
    __shared__ float s_sc[HDIM], s_sf[HDIM];
    int tid = threadIdx.x;
    if (tid < HDIM) {
        float inv_n = 1.0f / (float)n;
        float mean = g_stats[NLAYERS - 1][tid] * inv_n;
        float var = g_stats[NLAYERS - 1][HDIM + tid] * inv_n - mean * mean;
        float inv = rsqrtf(var + BN_EPS);
        float sc = gamma[tid] * inv;
        s_sc[tid] = sc;
        s_sf[tid] = beta[tid] - mean * sc;
    }
#pragma unroll
    for (int i = tid; i < HDIM * HC; i += 256) W1sm[i] = W1[i];
    __syncthreads();

    int lane = tid & 31;
    int warp = tid >> 5;
    float b1v = b1[lane];
    float w2v = W2[lane];
    float b2v = b2[0];
    float sc0 = s_sc[lane],      sf0 = s_sf[lane];
    float sc1 = s_sc[lane + 32], sf1 = s_sf[lane + 32];
    int base = blockIdx.x * 64 + warp * 8;

    for (int i = 0; i < 8; i++) {
        int node = base + i;
        if (node >= n) break;
        float h0 = fmaxf(fmaf(g_agg[node * HDIM + lane],      sc0, sf0), 0.f);
        float h1 = fmaxf(fmaf(g_agg[node * HDIM + 32 + lane], sc1, sf1), 0.f);
        float acc = b1v;
#pragma unroll
        for (int k = 0; k < 32; k++)
            acc = fmaf(__shfl_sync(0xFFFFFFFFu, h0, k), W1sm[k * HC + lane], acc);
#pragma unroll
        for (int k = 0; k < 32; k++)
            acc = fmaf(__shfl_sync(0xFFFFFFFFu, h1, k), W1sm[(k + 32) * HC + lane], acc);
        float r = fmaxf(acc, 0.0f) * w2v;
#pragma unroll
        for (int off = 16; off > 0; off >>= 1)
            r += __shfl_xor_sync(0xFFFFFFFFu, r, off);
        if (lane == 0) out[node] = r + b2v;
    }
}

// ---------------------------------------------------------------------------
extern "C" void kernel_launch(void* const* d_in, const int* in_sizes, int n_in,
                              void* d_out, int out_size) {
    const float* x        = (const float*)d_in[0];
    const int*   ei       = (const int*)d_in[1];
    const float* W_in     = (const float*)d_in[2];
    const float* b_in     = (const float*)d_in[3];
    const float* conv_W   = (const float*)d_in[4];
    // d_in[5] = conv_b : cancels exactly inside BatchNorm -> unused
    const float* bn_gamma = (const float*)d_in[6];
    const float* bn_beta  = (const float*)d_in[7];
    const float* W1       = (const float*)d_in[8];
    const float* b1       = (const float*)d_in[9];
    const float* W2       = (const float*)d_in[10];
    const float* b2       = (const float*)d_in[11];
    float* out = (float*)d_out;

    int n = in_sizes[0] / 5;
    int e = in_sizes[1] / 2;
    int nb = (n + SCAN_BLK - 1) / SCAN_BLK;

    k_count_deg<<<(e + 255) / 256, 256>>>(ei + e, e, conv_W);
    k_scan_fused<<<nb, 256>>>(n, e);
    k_bucket<<<(e + 255) / 256, 256>>>(ei, e, n);

    int gemm_blocks = (n + GROWS - 1) / GROWS;
    int agg_blocks = (n + AGG_WARPS * NODES_PER_WARP - 1) / (AGG_WARPS * NODES_PER_WARP);

    for (int l = 0; l < NLAYERS; l++) {
        k_gemm_mma<<<gemm_blocks, 256>>>(
            n, l, x, W_in, b_in,
            l > 0 ? bn_gamma + (l - 1) * HDIM : nullptr,
            l > 0 ? bn_beta + (l - 1) * HDIM : nullptr);
        k_aggregate<<<agg_blocks, 256>>>(n, l);
    }

    k_classifier<<<(n + 63) / 64, 256>>>(
        W1, b1, W2, b2,
        bn_gamma + (NLAYERS - 1) * HDIM, bn_beta + (NLAYERS - 1) * HDIM, out, n);
}

// round 10
// speedup vs baseline: 1.1057x; 1.0129x over previous
#include <cuda_runtime.h>
#include <cuda_fp16.h>

#define NMAX 100000
#define EMAX 1600000
#define HDIM 64
#define HC 32
#define NLAYERS 3
#define BN_EPS 1e-5f
#define SCAN_BLK 1024
#define SCAN_MAXB 128

// ---- scratch (device globals; no allocation allowed) ----
__device__ __half2 g_hs2[NMAX * 32];       // (h @ W) * dinv[row], fp16 pairs
__device__ float g_agg[NMAX * HDIM];       // pre-BN aggregated features (fp32)
__device__ int   g_cnt [NMAX];             // in-degree counts (left at 0 on exit)
__device__ float g_dinv[NMAX];             // (deg+1)^-1/2
__device__ int   g_row [NMAX + 1];         // CSR row pointers (by dst)
__device__ int   g_rank[EMAX];             // per-edge rank within its dst bucket
__device__ int   g_srcs[EMAX];             // src node ids sorted by dst
__device__ volatile int g_part[SCAN_MAXB]; // lookback partials (total+1)
__device__ float g_stats[NLAYERS][2 * HDIM]; // per-layer channel sum, sumsq
__device__ __half g_w16[NLAYERS][HDIM * HDIM]; // conv weights pre-converted fp16

static __device__ __forceinline__ unsigned s2u(const void* p) {
    return (unsigned)__cvta_generic_to_shared(p);
}

// ---------------------------------------------------------------------------
// count in-degrees, record per-edge rank; block 0 zeroes partials + BN stats;
// blocks 1..NLAYERS convert conv_W[layer] to fp16.
__global__ void k_count_deg(const int* __restrict__ dst, int e,
                            const float* __restrict__ conv_W) {
    int i = blockIdx.x * blockDim.x + threadIdx.x;
    if (blockIdx.x == 0) {
        if (threadIdx.x < SCAN_MAXB) *(int*)&g_part[threadIdx.x] = 0;
        for (int j = threadIdx.x; j < NLAYERS * 2 * HDIM; j += 256)
            (&g_stats[0][0])[j] = 0.0f;
    } else if (blockIdx.x <= NLAYERS) {
        int l = blockIdx.x - 1;
        const float* W = conv_W + l * HDIM * HDIM;
        for (int j = threadIdx.x; j < HDIM * HDIM / 4; j += 256) {
            float4 w = *reinterpret_cast<const float4*>(&W[j * 4]);
            __half2 h0 = __floats2half2_rn(w.x, w.y);
            __half2 h1 = __floats2half2_rn(w.z, w.w);
            uint2 pk;
            pk.x = *reinterpret_cast<unsigned*>(&h0);
            pk.y = *reinterpret_cast<unsigned*>(&h1);
            *reinterpret_cast<uint2*>(&g_w16[l][j * 4]) = pk;
        }
    }
    if (i < e) g_rank[i] = atomicAdd(&g_cnt[dst[i]], 1);
}

// fused scan: dinv + exclusive prefix (decoupled lookback) -> g_row
__global__ void k_scan_fused(int n, int e) {
    __shared__ int sh[256];
    int tid = threadIdx.x, b = blockIdx.x;
    int base = b * SCAN_BLK + tid * 4;

    int v[4]; int mine = 0;
    if (base + 4 <= n) {
        int4 c = *reinterpret_cast<const int4*>(&g_cnt[base]);
        v[0] = c.x; v[1] = c.y; v[2] = c.z; v[3] = c.w;
        g_dinv[base + 0] = rsqrtf((float)c.x + 1.0f);
        g_dinv[base + 1] = rsqrtf((float)c.y + 1.0f);
        g_dinv[base + 2] = rsqrtf((float)c.z + 1.0f);
        g_dinv[base + 3] = rsqrtf((float)c.w + 1.0f);
        mine = c.x + c.y + c.z + c.w;
    } else {
#pragma unroll
        for (int k = 0; k < 4; k++) {
            v[k] = 0;
            if (base + k < n) {
                int c = g_cnt[base + k];
                v[k] = c;
                g_dinv[base + k] = rsqrtf((float)c + 1.0f);
                mine += c;
            }
        }
    }

    sh[tid] = mine;
    __syncthreads();
    for (int o = 1; o < 256; o <<= 1) {
        int t = (tid >= o) ? sh[tid - o] : 0;
        __syncthreads();
        sh[tid] += t;
        __syncthreads();
    }
    int excl = sh[tid] - mine;
    int total = sh[255];

    if (tid == 0) atomicExch((int*)&g_part[b], total + 1);
    int pref = 0;
    for (int i = tid; i < b; i += 256) {
        int p;
        while ((p = g_part[i]) == 0) {}
        pref += p - 1;
    }
    __syncthreads();
    sh[tid] = pref;
    __syncthreads();
    for (int o = 128; o > 0; o >>= 1) {
        if (tid < o) sh[tid] += sh[tid + o];
        __syncthreads();
    }
    int off = sh[0] + excl;

#pragma unroll
    for (int k = 0; k < 4; k++) {
        int idx = base + k;
        if (idx < n) {
            g_row[idx] = off;
            off += v[k];
        }
    }
    if (b == 0 && tid == 0) g_row[n] = e;
}

// bucket placement: pure store using precomputed rank; re-zero g_cnt
__global__ void k_bucket(const int* __restrict__ ei, int e, int n) {
    int i = blockIdx.x * blockDim.x + threadIdx.x;
    if (i < n) g_cnt[i] = 0;
    if (i >= e) return;
    int s = ei[i];
    int d = ei[e + i];
    g_srcs[g_row[d] + g_rank[i]] = s;
}

// ---------------------------------------------------------------------------
// Tensor-core GEMM (exact R8 structure): 128 nodes x 64 cols, 8 warps.
#define GROWS 128
#define ASTRIDE 72   // halves; 144B rows: 16B aligned, ldmatrix conflict-free
__global__ void __launch_bounds__(256) k_gemm_mma(
    int n, int layer,
    const float* __restrict__ x, const float* __restrict__ Win,
    const float* __restrict__ bin,
    const float* __restrict__ gamma, const float* __restrict__ beta) {
    __shared__ __half Asm[GROWS * ASTRIDE];
    __shared__ __half Wsm[HDIM * ASTRIDE];
    __shared__ float s_sc[HDIM], s_sf[HDIM];

    int tid = threadIdx.x;
    int node0 = blockIdx.x * GROWS;

    if (layer > 0) {
        if (tid < HDIM) {
            float inv_n = 1.0f / (float)n;
            float mean = g_stats[layer - 1][tid] * inv_n;
            float var = g_stats[layer - 1][HDIM + tid] * inv_n - mean * mean;
            float inv = rsqrtf(var + BN_EPS);
            float sc = gamma[tid] * inv;
            s_sc[tid] = sc;
            s_sf[tid] = beta[tid] - mean * sc;
        }
        __syncthreads();
    }

    // W (64x64 fp16, pre-converted) -> smem, uint4 = 8 halves
    for (int i = tid; i < HDIM * HDIM / 8; i += 256) {
        uint4 w = *reinterpret_cast<const uint4*>(&g_w16[layer][i * 8]);
        int r = i >> 3;
        int c = (i * 8) & 63;
        *reinterpret_cast<uint4*>(&Wsm[r * ASTRIDE + c]) = w;
    }

    // A tile (128 x 64) -> fp16 smem, fused BN/relu or input-proj
#pragma unroll
    for (int it = 0; it < 8; it++) {
        int idx = tid + it * 256;
        int row = idx >> 4;
        int c4 = (idx & 15) * 4;
        int node = node0 + row;
        float4 v = make_float4(0.f, 0.f, 0.f, 0.f);
        if (node < n) {
            if (layer > 0) {
                v = *reinterpret_cast<const float4*>(&g_agg[node * HDIM + c4]);
                v.x = fmaf(v.x, s_sc[c4 + 0], s_sf[c4 + 0]);
                v.y = fmaf(v.y, s_sc[c4 + 1], s_sf[c4 + 1]);
                v.z = fmaf(v.z, s_sc[c4 + 2], s_sf[c4 + 2]);
                v.w = fmaf(v.w, s_sc[c4 + 3], s_sf[c4 + 3]);
            } else {
                v = *reinterpret_cast<const float4*>(&bin[c4]);
#pragma unroll
                for (int k = 0; k < 5; k++) {
                    float xv = __ldg(&x[node * 5 + k]);
                    float4 w = *reinterpret_cast<const float4*>(&Win[k * HDIM + c4]);
                    v.x = fmaf(xv, w.x, v.x);
                    v.y = fmaf(xv, w.y, v.y);
                    v.z = fmaf(xv, w.z, v.z);
                    v.w = fmaf(xv, w.w, v.w);
                }
            }
            v.x = fmaxf(v.x, 0.f); v.y = fmaxf(v.y, 0.f);
            v.z = fmaxf(v.z, 0.f); v.w = fmaxf(v.w, 0.f);
        }
        __half2 h0 = __floats2half2_rn(v.x, v.y);
        __half2 h1 = __floats2half2_rn(v.z, v.w);
        uint2 pk;
        pk.x = *reinterpret_cast<unsigned*>(&h0);
        pk.y = *reinterpret_cast<unsigned*>(&h1);
        *reinterpret_cast<uint2*>(&Asm[row * ASTRIDE + c4]) = pk;
    }
    __syncthreads();

    int warp = tid >> 5, lane = tid & 31;
    int wrow = warp * 16;

    // A fragments for all 4 k-steps (m16k16 each)
    unsigned a[4][4];
    {
        int r = lane & 15;
        int cb = (lane >> 4) << 3;
#pragma unroll
        for (int ks = 0; ks < 4; ks++) {
            unsigned addr = s2u(&Asm[(wrow + r) * ASTRIDE + ks * 16 + cb]);
            asm volatile("ldmatrix.sync.aligned.m8n8.x4.shared.b16 {%0,%1,%2,%3}, [%4];"
                         : "=r"(a[ks][0]), "=r"(a[ks][1]), "=r"(a[ks][2]), "=r"(a[ks][3])
                         : "r"(addr));
        }
    }

    float acc[8][4];
#pragma unroll
    for (int nt = 0; nt < 8; nt++)
#pragma unroll
        for (int q = 0; q < 4; q++) acc[nt][q] = 0.0f;

#pragma unroll
    for (int nt = 0; nt < 8; nt++) {
#pragma unroll
        for (int ks = 0; ks < 4; ks++) {
            unsigned b0, b1;
            int r = lane & 15;
            unsigned baddr = s2u(&Wsm[(ks * 16 + r) * ASTRIDE + nt * 8]);
            asm volatile("ldmatrix.sync.aligned.m8n8.x2.trans.shared.b16 {%0,%1}, [%2];"
                         : "=r"(b0), "=r"(b1) : "r"(baddr));
            asm volatile(
                "mma.sync.aligned.m16n8k16.row.col.f32.f16.f16.f32 "
                "{%0,%1,%2,%3}, {%4,%5,%6,%7}, {%8,%9}, {%0,%1,%2,%3};"
                : "+f"(acc[nt][0]), "+f"(acc[nt][1]), "+f"(acc[nt][2]), "+f"(acc[nt][3])
                : "r"(a[ks][0]), "r"(a[ks][1]), "r"(a[ks][2]), "r"(a[ks][3]),
                  "r"(b0), "r"(b1));
        }
    }

    // epilogue: scale by dinv, pack fp16, store
    int gr = lane >> 2;
    int qp = lane & 3;
    int node_a = node0 + wrow + gr;
    int node_b = node_a + 8;
    float dia = (node_a < n) ? g_dinv[node_a] : 0.f;
    float dib = (node_b < n) ? g_dinv[node_b] : 0.f;
#pragma unroll
    for (int nt = 0; nt < 8; nt++) {
        if (node_a < n)
            g_hs2[node_a * 32 + nt * 4 + qp] =
                __floats2half2_rn(acc[nt][0] * dia, acc[nt][1] * dia);
        if (node_b < n)
            g_hs2[node_b * 32 + nt * 4 + qp] =
                __floats2half2_rn(acc[nt][2] * dib, acc[nt][3] * dib);
    }
}

// ---------------------------------------------------------------------------
// pull-based aggregation + BN stats (exact R5 loop)
#define AGG_WARPS 8
#define NODES_PER_WARP 8
__global__ void k_aggregate(int n, int layer) {
    __shared__ float s_sum[HDIM], s_sq[HDIM];
    int tid = threadIdx.x, lane = tid & 31, warp = tid >> 5;
    if (tid < HDIM) { s_sum[tid] = 0.f; s_sq[tid] = 0.f; }
    __syncthreads();

    float ls0 = 0.f, lq0 = 0.f, ls1 = 0.f, lq1 = 0.f;
    int node0 = (blockIdx.x * AGG_WARPS + warp) * NODES_PER_WARP;

    for (int i = 0; i < NODES_PER_WARP; i++) {
        int node = node0 + i;
        if (node >= n) break;
        int beg = g_row[node], end = g_row[node + 1];
        float a0 = 0.f, a1 = 0.f;
        int j = beg;
        for (; j + 8 <= end; j += 8) {
            int ss[8];
#pragma unroll
            for (int u = 0; u < 8; u++) ss[u] = g_srcs[j + u];
            float2 f[8];
#pragma unroll
            for (int u = 0; u < 8; u++)
                f[u] = __half22float2(g_hs2[ss[u] * 32 + lane]);
#pragma unroll
            for (int u = 0; u < 8; u++) { a0 += f[u].x; a1 += f[u].y; }
        }
        for (; j < end; j++) {
            float2 f = __half22float2(g_hs2[g_srcs[j] * 32 + lane]);
            a0 += f.x; a1 += f.y;
        }
        float2 self = __half22float2(g_hs2[node * 32 + lane]);
        float di = g_dinv[node];
        a0 = (a0 + self.x) * di;
        a1 = (a1 + self.y) * di;
        float2 o; o.x = a0; o.y = a1;
        *reinterpret_cast<float2*>(&g_agg[node * HDIM + 2 * lane]) = o;
        ls0 += a0; lq0 = fmaf(a0, a0, lq0);
        ls1 += a1; lq1 = fmaf(a1, a1, lq1);
    }

    atomicAdd(&s_sum[2 * lane], ls0);
    atomicAdd(&s_sq[2 * lane], lq0);
    atomicAdd(&s_sum[2 * lane + 1], ls1);
    atomicAdd(&s_sq[2 * lane + 1], lq1);
    __syncthreads();
    if (tid < HDIM) {
        atomicAdd(&g_stats[layer][tid], s_sum[tid]);
        atomicAdd(&g_stats[layer][HDIM + tid], s_sq[tid]);
    }
}

// ---------------------------------------------------------------------------
// classifier with in-block final BN+ReLU: out = relu(bn(agg) @ W1 + b1) @ W2 + b2
__global__ void k_classifier(const float* __restrict__ W1,
                             const float* __restrict__ b1,
                             const float* __restrict__ W2,
                             const float* __restrict__ b2,
                             const float* __restrict__ gamma,
                             const float* __restrict__ beta,
                             float* __restrict__ out, int n) {
    __shared__ float W1sm[HDIM * HC];
    __shared__ float s_sc[HDIM], s_sf[HDIM];
    int tid = threadIdx.x;
    if (tid < HDIM) {
        float inv_n = 1.0f / (float)n;
        float mean = g_stats[NLAYERS - 1][tid] * inv_n;
        float var = g_stats[NLAYERS - 1][HDIM + tid] * inv_n - mean * mean;
        float inv = rsqrtf(var + BN_EPS);
        float sc = gamma[tid] * inv;
        s_sc[tid] = sc;
        s_sf[tid] = beta[tid] - mean * sc;
    }
#pragma unroll
    for (int i = tid; i < HDIM * HC; i += 256) W1sm[i] = W1[i];
    __syncthreads();

    int lane = tid & 31;
    int warp = tid >> 5;
    float b1v = b1[lane];
    float w2v = W2[lane];
    float b2v = b2[0];
    float sc0 = s_sc[lane],      sf0 = s_sf[lane];
    float sc1 = s_sc[lane + 32], sf1 = s_sf[lane + 32];
    int base = blockIdx.x * 64 + warp * 8;

    for (int i = 0; i < 8; i++) {
        int node = base + i;
        if (node >= n) break;
        float h0 = fmaxf(fmaf(g_agg[node * HDIM + lane],      sc0, sf0), 0.f);
        float h1 = fmaxf(fmaf(g_agg[node * HDIM + 32 + lane], sc1, sf1), 0.f);
        float acc = b1v;
#pragma unroll
        for (int k = 0; k < 32; k++)
            acc = fmaf(__shfl_sync(0xFFFFFFFFu, h0, k), W1sm[k * HC + lane], acc);
#pragma unroll
        for (int k = 0; k < 32; k++)
            acc = fmaf(__shfl_sync(0xFFFFFFFFu, h1, k), W1sm[(k + 32) * HC + lane], acc);
        float r = fmaxf(acc, 0.0f) * w2v;
#pragma unroll
        for (int off = 16; off > 0; off >>= 1)
            r += __shfl_xor_sync(0xFFFFFFFFu, r, off);
        if (lane == 0) out[node] = r + b2v;
    }
}

// ---------------------------------------------------------------------------
extern "C" void kernel_launch(void* const* d_in, const int* in_sizes, int n_in,
                              void* d_out, int out_size) {
    const float* x        = (const float*)d_in[0];
    const int*   ei       = (const int*)d_in[1];
    const float* W_in     = (const float*)d_in[2];
    const float* b_in     = (const float*)d_in[3];
    const float* conv_W   = (const float*)d_in[4];
    // d_in[5] = conv_b : cancels exactly inside BatchNorm -> unused
    const float* bn_gamma = (const float*)d_in[6];
    const float* bn_beta  = (const float*)d_in[7];
    const float* W1       = (const float*)d_in[8];
    const float* b1       = (const float*)d_in[9];
    const float* W2       = (const float*)d_in[10];
    const float* b2       = (const float*)d_in[11];
    float* out = (float*)d_out;

    int n = in_sizes[0] / 5;
    int e = in_sizes[1] / 2;
    int nb = (n + SCAN_BLK - 1) / SCAN_BLK;

    k_count_deg<<<(e + 255) / 256, 256>>>(ei + e, e, conv_W);
    k_scan_fused<<<nb, 256>>>(n, e);
    k_bucket<<<(e + 255) / 256, 256>>>(ei, e, n);

    int gemm_blocks = (n + GROWS - 1) / GROWS;
    int agg_blocks = (n + AGG_WARPS * NODES_PER_WARP - 1) / (AGG_WARPS * NODES_PER_WARP);

    for (int l = 0; l < NLAYERS; l++) {
        k_gemm_mma<<<gemm_blocks, 256>>>(
            n, l, x, W_in, b_in,
            l > 0 ? bn_gamma + (l - 1) * HDIM : nullptr,
            l > 0 ? bn_beta + (l - 1) * HDIM : nullptr);
        k_aggregate<<<agg_blocks, 256>>>(n, l);
    }

    k_classifier<<<(n + 63) / 64, 256>>>(
        W1, b1, W2, b2,
        bn_gamma + (NLAYERS - 1) * HDIM, bn_beta + (NLAYERS - 1) * HDIM, out, n);
}

// round 11
// speedup vs baseline: 1.1067x; 1.0008x over previous
#include <cuda_runtime.h>
#include <cuda_fp16.h>

#define NMAX 100000
#define EMAX 1600000
#define EPAD (EMAX + 8 * NMAX)
#define HDIM 64
#define HC 32
#define NLAYERS 3
#define BN_EPS 1e-5f
#define SCAN_BLK 1024
#define SCAN_MAXB 128

// ---- scratch (device globals; no allocation allowed) ----
__device__ __half2 g_hs2[(NMAX + 1) * 32]; // (h @ W) * dinv[row]; row n = zero sentinel
__device__ float g_agg[NMAX * HDIM];       // pre-BN aggregated features (fp32)
__device__ int   g_cnt [NMAX];             // in-degree counts (left at 0 on exit)
__device__ float g_dinv[NMAX];             // (deg+1)^-1/2
__device__ int   g_row [NMAX + 1];         // padded CSR row pointers (by dst)
__device__ int   g_rank[EMAX];             // per-edge rank within its dst bucket
__device__ int   g_srcs[EPAD];             // src ids sorted by dst, padded to 8
__device__ volatile int g_part[SCAN_MAXB]; // lookback partials (total+1)
__device__ float g_stats[NLAYERS][2 * HDIM]; // per-layer channel sum, sumsq
__device__ __half g_w16[NLAYERS][HDIM * HDIM]; // conv weights pre-converted fp16

static __device__ __forceinline__ unsigned s2u(const void* p) {
    return (unsigned)__cvta_generic_to_shared(p);
}

// ---------------------------------------------------------------------------
// count in-degrees, record per-edge rank; block 0 zeroes partials + BN stats;
// blocks 1..NLAYERS convert conv_W[layer] to fp16; block NLAYERS+1 zeroes the
// sentinel hs2 row (row n).
__global__ void k_count_deg(const int* __restrict__ dst, int e, int n,
                            const float* __restrict__ conv_W) {
    int i = blockIdx.x * blockDim.x + threadIdx.x;
    if (blockIdx.x == 0) {
        if (threadIdx.x < SCAN_MAXB) *(int*)&g_part[threadIdx.x] = 0;
        for (int j = threadIdx.x; j < NLAYERS * 2 * HDIM; j += 256)
            (&g_stats[0][0])[j] = 0.0f;
    } else if (blockIdx.x <= NLAYERS) {
        int l = blockIdx.x - 1;
        const float* W = conv_W + l * HDIM * HDIM;
        for (int j = threadIdx.x; j < HDIM * HDIM / 4; j += 256) {
            float4 w = *reinterpret_cast<const float4*>(&W[j * 4]);
            __half2 h0 = __floats2half2_rn(w.x, w.y);
            __half2 h1 = __floats2half2_rn(w.z, w.w);
            uint2 pk;
            pk.x = *reinterpret_cast<unsigned*>(&h0);
            pk.y = *reinterpret_cast<unsigned*>(&h1);
            *reinterpret_cast<uint2*>(&g_w16[l][j * 4]) = pk;
        }
    } else if (blockIdx.x == NLAYERS + 1) {
        if (threadIdx.x < 32)
            g_hs2[n * 32 + threadIdx.x] = __floats2half2_rn(0.f, 0.f);
    }
    if (i < e) g_rank[i] = atomicAdd(&g_cnt[dst[i]], 1);
}

// fused scan: dinv from real counts + exclusive prefix of PADDED counts
__global__ void k_scan_fused(int n) {
    __shared__ int sh[256];
    int tid = threadIdx.x, b = blockIdx.x;
    int base = b * SCAN_BLK + tid * 4;

    int v[4]; int mine = 0;
    if (base + 4 <= n) {
        int4 c = *reinterpret_cast<const int4*>(&g_cnt[base]);
        g_dinv[base + 0] = rsqrtf((float)c.x + 1.0f);
        g_dinv[base + 1] = rsqrtf((float)c.y + 1.0f);
        g_dinv[base + 2] = rsqrtf((float)c.z + 1.0f);
        g_dinv[base + 3] = rsqrtf((float)c.w + 1.0f);
        v[0] = (c.x + 7) & ~7; v[1] = (c.y + 7) & ~7;
        v[2] = (c.z + 7) & ~7; v[3] = (c.w + 7) & ~7;
        mine = v[0] + v[1] + v[2] + v[3];
    } else {
#pragma unroll
        for (int k = 0; k < 4; k++) {
            v[k] = 0;
            if (base + k < n) {
                int c = g_cnt[base + k];
                g_dinv[base + k] = rsqrtf((float)c + 1.0f);
                v[k] = (c + 7) & ~7;
                mine += v[k];
            }
        }
    }

    sh[tid] = mine;
    __syncthreads();
    for (int o = 1; o < 256; o <<= 1) {
        int t = (tid >= o) ? sh[tid - o] : 0;
        __syncthreads();
        sh[tid] += t;
        __syncthreads();
    }
    int excl = sh[tid] - mine;
    int total = sh[255];

    if (tid == 0) atomicExch((int*)&g_part[b], total + 1);
    int pref = 0;
    for (int i = tid; i < b; i += 256) {
        int p;
        while ((p = g_part[i]) == 0) {}
        pref += p - 1;
    }
    __syncthreads();
    sh[tid] = pref;
    __syncthreads();
    for (int o = 128; o > 0; o >>= 1) {
        if (tid < o) sh[tid] += sh[tid + o];
        __syncthreads();
    }
    int off = sh[0] + excl;

#pragma unroll
    for (int k = 0; k < 4; k++) {
        int idx = base + k;
        if (idx < n) {
            g_row[idx] = off;
            off += v[k];
            if (idx == n - 1) g_row[n] = off;
        }
    }
}

// bucket placement + pad fill with sentinel n; re-zero g_cnt
__global__ void k_bucket(const int* __restrict__ ei, int e, int n) {
    int i = blockIdx.x * blockDim.x + threadIdx.x;
    if (i < n) {
        int c = g_cnt[i];
        int pc = (c + 7) & ~7;
        int base = g_row[i];
        for (int k = c; k < pc; k++) g_srcs[base + k] = n;
        g_cnt[i] = 0;
    }
    if (i >= e) return;
    int s = ei[i];
    int d = ei[e + i];
    g_srcs[g_row[d] + g_rank[i]] = s;
}

// ---------------------------------------------------------------------------
// Tensor-core GEMM (exact R8/R10 structure): 128 nodes x 64 cols, 8 warps.
#define GROWS 128
#define ASTRIDE 72   // halves; 144B rows: 16B aligned, ldmatrix conflict-free
__global__ void __launch_bounds__(256) k_gemm_mma(
    int n, int layer,
    const float* __restrict__ x, const float* __restrict__ Win,
    const float* __restrict__ bin,
    const float* __restrict__ gamma, const float* __restrict__ beta) {
    __shared__ __half Asm[GROWS * ASTRIDE];
    __shared__ __half Wsm[HDIM * ASTRIDE];
    __shared__ float s_sc[HDIM], s_sf[HDIM];

    int tid = threadIdx.x;
    int node0 = blockIdx.x * GROWS;

    if (layer > 0) {
        if (tid < HDIM) {
            float inv_n = 1.0f / (float)n;
            float mean = g_stats[layer - 1][tid] * inv_n;
            float var = g_stats[layer - 1][HDIM + tid] * inv_n - mean * mean;
            float inv = rsqrtf(var + BN_EPS);
            float sc = gamma[tid] * inv;
            s_sc[tid] = sc;
            s_sf[tid] = beta[tid] - mean * sc;
        }
        __syncthreads();
    }

    // W (64x64 fp16, pre-converted) -> smem, uint4 = 8 halves
    for (int i = tid; i < HDIM * HDIM / 8; i += 256) {
        uint4 w = *reinterpret_cast<const uint4*>(&g_w16[layer][i * 8]);
        int r = i >> 3;
        int c = (i * 8) & 63;
        *reinterpret_cast<uint4*>(&Wsm[r * ASTRIDE + c]) = w;
    }

    // A tile (128 x 64) -> fp16 smem, fused BN/relu or input-proj
#pragma unroll
    for (int it = 0; it < 8; it++) {
        int idx = tid + it * 256;
        int row = idx >> 4;
        int c4 = (idx & 15) * 4;
        int node = node0 + row;
        float4 v = make_float4(0.f, 0.f, 0.f, 0.f);
        if (node < n) {
            if (layer > 0) {
                v = *reinterpret_cast<const float4*>(&g_agg[node * HDIM + c4]);
                v.x = fmaf(v.x, s_sc[c4 + 0], s_sf[c4 + 0]);
                v.y = fmaf(v.y, s_sc[c4 + 1], s_sf[c4 + 1]);
                v.z = fmaf(v.z, s_sc[c4 + 2], s_sf[c4 + 2]);
                v.w = fmaf(v.w, s_sc[c4 + 3], s_sf[c4 + 3]);
            } else {
                v = *reinterpret_cast<const float4*>(&bin[c4]);
#pragma unroll
                for (int k = 0; k < 5; k++) {
                    float xv = __ldg(&x[node * 5 + k]);
                    float4 w = *reinterpret_cast<const float4*>(&Win[k * HDIM + c4]);
                    v.x = fmaf(xv, w.x, v.x);
                    v.y = fmaf(xv, w.y, v.y);
                    v.z = fmaf(xv, w.z, v.z);
                    v.w = fmaf(xv, w.w, v.w);
                }
            }
            v.x = fmaxf(v.x, 0.f); v.y = fmaxf(v.y, 0.f);
            v.z = fmaxf(v.z, 0.f); v.w = fmaxf(v.w, 0.f);
        }
        __half2 h0 = __floats2half2_rn(v.x, v.y);
        __half2 h1 = __floats2half2_rn(v.z, v.w);
        uint2 pk;
        pk.x = *reinterpret_cast<unsigned*>(&h0);
        pk.y = *reinterpret_cast<unsigned*>(&h1);
        *reinterpret_cast<uint2*>(&Asm[row * ASTRIDE + c4]) = pk;
    }
    __syncthreads();

    int warp = tid >> 5, lane = tid & 31;
    int wrow = warp * 16;

    // A fragments for all 4 k-steps (m16k16 each)
    unsigned a[4][4];
    {
        int r = lane & 15;
        int cb = (lane >> 4) << 3;
#pragma unroll
        for (int ks = 0; ks < 4; ks++) {
            unsigned addr = s2u(&Asm[(wrow + r) * ASTRIDE + ks * 16 + cb]);
            asm volatile("ldmatrix.sync.aligned.m8n8.x4.shared.b16 {%0,%1,%2,%3}, [%4];"
                         : "=r"(a[ks][0]), "=r"(a[ks][1]), "=r"(a[ks][2]), "=r"(a[ks][3])
                         : "r"(addr));
        }
    }

    float acc[8][4];
#pragma unroll
    for (int nt = 0; nt < 8; nt++)
#pragma unroll
        for (int q = 0; q < 4; q++) acc[nt][q] = 0.0f;

#pragma unroll
    for (int nt = 0; nt < 8; nt++) {
#pragma unroll
        for (int ks = 0; ks < 4; ks++) {
            unsigned b0, b1;
            int r = lane & 15;
            unsigned baddr = s2u(&Wsm[(ks * 16 + r) * ASTRIDE + nt * 8]);
            asm volatile("ldmatrix.sync.aligned.m8n8.x2.trans.shared.b16 {%0,%1}, [%2];"
                         : "=r"(b0), "=r"(b1) : "r"(baddr));
            asm volatile(
                "mma.sync.aligned.m16n8k16.row.col.f32.f16.f16.f32 "
                "{%0,%1,%2,%3}, {%4,%5,%6,%7}, {%8,%9}, {%0,%1,%2,%3};"
                : "+f"(acc[nt][0]), "+f"(acc[nt][1]), "+f"(acc[nt][2]), "+f"(acc[nt][3])
                : "r"(a[ks][0]), "r"(a[ks][1]), "r"(a[ks][2]), "r"(a[ks][3]),
                  "r"(b0), "r"(b1));
        }
    }

    // epilogue: scale by dinv, pack fp16, store
    int gr = lane >> 2;
    int qp = lane & 3;
    int node_a = node0 + wrow + gr;
    int node_b = node_a + 8;
    float dia = (node_a < n) ? g_dinv[node_a] : 0.f;
    float dib = (node_b < n) ? g_dinv[node_b] : 0.f;
#pragma unroll
    for (int nt = 0; nt < 8; nt++) {
        if (node_a < n)
            g_hs2[node_a * 32 + nt * 4 + qp] =
                __floats2half2_rn(acc[nt][0] * dia, acc[nt][1] * dia);
        if (node_b < n)
            g_hs2[node_b * 32 + nt * 4 + qp] =
                __floats2half2_rn(acc[nt][2] * dib, acc[nt][3] * dib);
    }
}

// ---------------------------------------------------------------------------
// pull-based aggregation + BN stats. Buckets padded to multiples of 8 with
// sentinel node n (hs2 row = zeros): single clean 8-batch loop, int4 id loads.
#define AGG_WARPS 8
#define NODES_PER_WARP 8
__global__ void k_aggregate(int n, int layer) {
    __shared__ float s_sum[HDIM], s_sq[HDIM];
    int tid = threadIdx.x, lane = tid & 31, warp = tid >> 5;
    if (tid < HDIM) { s_sum[tid] = 0.f; s_sq[tid] = 0.f; }
    __syncthreads();

    float ls0 = 0.f, lq0 = 0.f, ls1 = 0.f, lq1 = 0.f;
    int node0 = (blockIdx.x * AGG_WARPS + warp) * NODES_PER_WARP;

    for (int i = 0; i < NODES_PER_WARP; i++) {
        int node = node0 + i;
        if (node >= n) break;
        int beg = g_row[node], end = g_row[node + 1];
        float a0 = 0.f, a1 = 0.f;
        for (int j = beg; j < end; j += 8) {
            int4 sa = *reinterpret_cast<const int4*>(&g_srcs[j]);
            int4 sb = *reinterpret_cast<const int4*>(&g_srcs[j + 4]);
            float2 f[8];
            f[0] = __half22float2(g_hs2[sa.x * 32 + lane]);
            f[1] = __half22float2(g_hs2[sa.y * 32 + lane]);
            f[2] = __half22float2(g_hs2[sa.z * 32 + lane]);
            f[3] = __half22float2(g_hs2[sa.w * 32 + lane]);
            f[4] = __half22float2(g_hs2[sb.x * 32 + lane]);
            f[5] = __half22float2(g_hs2[sb.y * 32 + lane]);
            f[6] = __half22float2(g_hs2[sb.z * 32 + lane]);
            f[7] = __half22float2(g_hs2[sb.w * 32 + lane]);
#pragma unroll
            for (int u = 0; u < 8; u++) { a0 += f[u].x; a1 += f[u].y; }
        }
        float2 self = __half22float2(g_hs2[node * 32 + lane]);
        float di = g_dinv[node];
        a0 = (a0 + self.x) * di;
        a1 = (a1 + self.y) * di;
        float2 o; o.x = a0; o.y = a1;
        *reinterpret_cast<float2*>(&g_agg[node * HDIM + 2 * lane]) = o;
        ls0 += a0; lq0 = fmaf(a0, a0, lq0);
        ls1 += a1; lq1 = fmaf(a1, a1, lq1);
    }

    atomicAdd(&s_sum[2 * lane], ls0);
    atomicAdd(&s_sq[2 * lane], lq0);
    atomicAdd(&s_sum[2 * lane + 1], ls1);
    atomicAdd(&s_sq[2 * lane + 1], lq1);
    __syncthreads();
    if (tid < HDIM) {
        atomicAdd(&g_stats[layer][tid], s_sum[tid]);
        atomicAdd(&g_stats[layer][HDIM + tid], s_sq[tid]);
    }
}

// ---------------------------------------------------------------------------
// classifier with in-block final BN+ReLU: out = relu(bn(agg) @ W1 + b1) @ W2 + b2
__global__ void k_classifier(const float* __restrict__ W1,
                             const float* __restrict__ b1,
                             const float* __restrict__ W2,
                             const float* __restrict__ b2,
                             const float* __restrict__ gamma,
                             const float* __restrict__ beta,
                             float* __restrict__ out, int n) {
    __shared__ float W1sm[HDIM * HC];
    __shared__ float s_sc[HDIM], s_sf[HDIM];
    int tid = threadIdx.x;
    if (tid < HDIM) {
        float inv_n = 1.0f / (float)n;
        float mean = g_stats[NLAYERS - 1][tid] * inv_n;
        float var = g_stats[NLAYERS - 1][HDIM + tid] * inv_n - mean * mean;
        float inv = rsqrtf(var + BN_EPS);
        float sc = gamma[tid] * inv;
        s_sc[tid] = sc;
        s_sf[tid] = beta[tid] - mean * sc;
    }
#pragma unroll
    for (int i = tid; i < HDIM * HC; i += 256) W1sm[i] = W1[i];
    __syncthreads();

    int lane = tid & 31;
    int warp = tid >> 5;
    float b1v = b1[lane];
    float w2v = W2[lane];
    float b2v = b2[0];
    float sc0 = s_sc[lane],      sf0 = s_sf[lane];
    float sc1 = s_sc[lane + 32], sf1 = s_sf[lane + 32];
    int base = blockIdx.x * 64 + warp * 8;

    for (int i = 0; i < 8; i++) {
        int node = base + i;
        if (node >= n) break;
        float h0 = fmaxf(fmaf(g_agg[node * HDIM + lane],      sc0, sf0), 0.f);
        float h1 = fmaxf(fmaf(g_agg[node * HDIM + 32 + lane], sc1, sf1), 0.f);
        float acc = b1v;
#pragma unroll
        for (int k = 0; k < 32; k++)
            acc = fmaf(__shfl_sync(0xFFFFFFFFu, h0, k), W1sm[k * HC + lane], acc);
#pragma unroll
        for (int k = 0; k < 32; k++)
            acc = fmaf(__shfl_sync(0xFFFFFFFFu, h1, k), W1sm[(k + 32) * HC + lane], acc);
        float r = fmaxf(acc, 0.0f) * w2v;
#pragma unroll
        for (int off = 16; off > 0; off >>= 1)
            r += __shfl_xor_sync(0xFFFFFFFFu, r, off);
        if (lane == 0) out[node] = r + b2v;
    }
}

// ---------------------------------------------------------------------------
extern "C" void kernel_launch(void* const* d_in, const int* in_sizes, int n_in,
                              void* d_out, int out_size) {
    const float* x        = (const float*)d_in[0];
    const int*   ei       = (const int*)d_in[1];
    const float* W_in     = (const float*)d_in[2];
    const float* b_in     = (const float*)d_in[3];
    const float* conv_W   = (const float*)d_in[4];
    // d_in[5] = conv_b : cancels exactly inside BatchNorm -> unused
    const float* bn_gamma = (const float*)d_in[6];
    const float* bn_beta  = (const float*)d_in[7];
    const float* W1       = (const float*)d_in[8];
    const float* b1       = (const float*)d_in[9];
    const float* W2       = (const float*)d_in[10];
    const float* b2       = (const float*)d_in[11];
    float* out = (float*)d_out;

    int n = in_sizes[0] / 5;
    int e = in_sizes[1] / 2;
    int nb = (n + SCAN_BLK - 1) / SCAN_BLK;

    k_count_deg<<<(e + 255) / 256, 256>>>(ei + e, e, n, conv_W);
    k_scan_fused<<<nb, 256>>>(n);
    k_bucket<<<(e + 255) / 256, 256>>>(ei, e, n);

    int gemm_blocks = (n + GROWS - 1) / GROWS;
    int agg_blocks = (n + AGG_WARPS * NODES_PER_WARP - 1) / (AGG_WARPS * NODES_PER_WARP);

    for (int l = 0; l < NLAYERS; l++) {
        k_gemm_mma<<<gemm_blocks, 256>>>(
            n, l, x, W_in, b_in,
            l > 0 ? bn_gamma + (l - 1) * HDIM : nullptr,
            l > 0 ? bn_beta + (l - 1) * HDIM : nullptr);
        k_aggregate<<<agg_blocks, 256>>>(n, l);
    }

    k_classifier<<<(n + 63) / 64, 256>>>(
        W1, b1, W2, b2,
        bn_gamma + (NLAYERS - 1) * HDIM, bn_beta + (NLAYERS - 1) * HDIM, out, n);
}

// round 13
// speedup vs baseline: 1.1496x; 1.0388x over previous
#include <cuda_runtime.h>
#include <cuda_fp16.h>

#define NMAX 100000
#define EMAX 1600000
#define EPAD (EMAX + 8 * NMAX)
#define HDIM 64
#define HC 32
#define NLAYERS 3
#define BN_EPS 1e-5f
#define SCAN_BLK 1024
#define SCAN_MAXB 128

// ---- scratch (device globals; no allocation allowed) ----
__device__ __half2 g_hs2[(NMAX + 1) * 32]; // (h @ W) * dinv[row]; row n = zero sentinel
__device__ float g_agg[NMAX * HDIM];       // pre-BN aggregated features (fp32)
__device__ int   g_cnt [NMAX];             // in-degree counts (left at 0 on exit)
__device__ float g_dinv[NMAX];             // (deg+1)^-1/2
__device__ int   g_row [NMAX + 1];         // padded CSR row pointers (by dst)
__device__ int   g_rank[EMAX];             // per-edge rank within its dst bucket
__device__ int   g_srcs[EPAD];             // src ids sorted by dst, padded to 8
__device__ volatile int g_part[SCAN_MAXB]; // lookback partials (total+1)
__device__ float g_stats[NLAYERS][2 * HDIM]; // per-layer channel sum, sumsq
__device__ __half g_w16[NLAYERS][HDIM * HDIM]; // conv weights pre-converted fp16

static __device__ __forceinline__ unsigned s2u(const void* p) {
    return (unsigned)__cvta_generic_to_shared(p);
}

// ---------------------------------------------------------------------------
// count in-degrees, record per-edge rank; block 0 zeroes partials + BN stats;
// blocks 1..NLAYERS convert conv_W[layer] to fp16; block NLAYERS+1 zeroes the
// sentinel hs2 row (row n).
__global__ void k_count_deg(const int* __restrict__ dst, int e, int n,
                            const float* __restrict__ conv_W) {
    int i = blockIdx.x * blockDim.x + threadIdx.x;
    if (blockIdx.x == 0) {
        if (threadIdx.x < SCAN_MAXB) *(int*)&g_part[threadIdx.x] = 0;
        for (int j = threadIdx.x; j < NLAYERS * 2 * HDIM; j += 256)
            (&g_stats[0][0])[j] = 0.0f;
    } else if (blockIdx.x <= NLAYERS) {
        int l = blockIdx.x - 1;
        const float* W = conv_W + l * HDIM * HDIM;
        for (int j = threadIdx.x; j < HDIM * HDIM / 4; j += 256) {
            float4 w = *reinterpret_cast<const float4*>(&W[j * 4]);
            __half2 h0 = __floats2half2_rn(w.x, w.y);
            __half2 h1 = __floats2half2_rn(w.z, w.w);
            uint2 pk;
            pk.x = *reinterpret_cast<unsigned*>(&h0);
            pk.y = *reinterpret_cast<unsigned*>(&h1);
            *reinterpret_cast<uint2*>(&g_w16[l][j * 4]) = pk;
        }
    } else if (blockIdx.x == NLAYERS + 1) {
        if (threadIdx.x < 32)
            g_hs2[n * 32 + threadIdx.x] = __floats2half2_rn(0.f, 0.f);
    }
    if (i < e) g_rank[i] = atomicAdd(&g_cnt[dst[i]], 1);
}

// fused scan: dinv from real counts + exclusive prefix of PADDED counts
__global__ void k_scan_fused(int n) {
    __shared__ int sh[256];
    int tid = threadIdx.x, b = blockIdx.x;
    int base = b * SCAN_BLK + tid * 4;

    int v[4]; int mine = 0;
    if (base + 4 <= n) {
        int4 c = *reinterpret_cast<const int4*>(&g_cnt[base]);
        g_dinv[base + 0] = rsqrtf((float)c.x + 1.0f);
        g_dinv[base + 1] = rsqrtf((float)c.y + 1.0f);
        g_dinv[base + 2] = rsqrtf((float)c.z + 1.0f);
        g_dinv[base + 3] = rsqrtf((float)c.w + 1.0f);
        v[0] = (c.x + 7) & ~7; v[1] = (c.y + 7) & ~7;
        v[2] = (c.z + 7) & ~7; v[3] = (c.w + 7) & ~7;
        mine = v[0] + v[1] + v[2] + v[3];
    } else {
#pragma unroll
        for (int k = 0; k < 4; k++) {
            v[k] = 0;
            if (base + k < n) {
                int c = g_cnt[base + k];
                g_dinv[base + k] = rsqrtf((float)c + 1.0f);
                v[k] = (c + 7) & ~7;
                mine += v[k];
            }
        }
    }

    sh[tid] = mine;
    __syncthreads();
    for (int o = 1; o < 256; o <<= 1) {
        int t = (tid >= o) ? sh[tid - o] : 0;
        __syncthreads();
        sh[tid] += t;
        __syncthreads();
    }
    int excl = sh[tid] - mine;
    int total = sh[255];

    if (tid == 0) atomicExch((int*)&g_part[b], total + 1);
    int pref = 0;
    for (int i = tid; i < b; i += 256) {
        int p;
        while ((p = g_part[i]) == 0) {}
        pref += p - 1;
    }
    __syncthreads();
    sh[tid] = pref;
    __syncthreads();
    for (int o = 128; o > 0; o >>= 1) {
        if (tid < o) sh[tid] += sh[tid + o];
        __syncthreads();
    }
    int off = sh[0] + excl;

#pragma unroll
    for (int k = 0; k < 4; k++) {
        int idx = base + k;
        if (idx < n) {
            g_row[idx] = off;
            off += v[k];
            if (idx == n - 1) g_row[n] = off;
        }
    }
}

// bucket placement + pad fill with sentinel n; re-zero g_cnt
__global__ void k_bucket(const int* __restrict__ ei, int e, int n) {
    int i = blockIdx.x * blockDim.x + threadIdx.x;
    if (i < n) {
        int c = g_cnt[i];
        int pc = (c + 7) & ~7;
        int base = g_row[i];
        for (int k = c; k < pc; k++) g_srcs[base + k] = n;
        g_cnt[i] = 0;
    }
    if (i >= e) return;
    int s = ei[i];
    int d = ei[e + i];
    g_srcs[g_row[d] + g_rank[i]] = s;
}

// ---------------------------------------------------------------------------
// Tensor-core GEMM (exact R10/R11 structure): 128 nodes x 64 cols, 8 warps.
#define GROWS 128
#define ASTRIDE 72   // halves; 144B rows: 16B aligned, ldmatrix conflict-free
__global__ void __launch_bounds__(256) k_gemm_mma(
    int n, int layer,
    const float* __restrict__ x, const float* __restrict__ Win,
    const float* __restrict__ bin,
    const float* __restrict__ gamma, const float* __restrict__ beta) {
    __shared__ __half Asm[GROWS * ASTRIDE];
    __shared__ __half Wsm[HDIM * ASTRIDE];
    __shared__ float s_sc[HDIM], s_sf[HDIM];

    int tid = threadIdx.x;
    int node0 = blockIdx.x * GROWS;

    if (layer > 0) {
        if (tid < HDIM) {
            float inv_n = 1.0f / (float)n;
            float mean = g_stats[layer - 1][tid] * inv_n;
            float var = g_stats[layer - 1][HDIM + tid] * inv_n - mean * mean;
            float inv = rsqrtf(var + BN_EPS);
            float sc = gamma[tid] * inv;
            s_sc[tid] = sc;
            s_sf[tid] = beta[tid] - mean * sc;
        }
        __syncthreads();
    }

    // W (64x64 fp16, pre-converted) -> smem, uint4 = 8 halves
    for (int i = tid; i < HDIM * HDIM / 8; i += 256) {
        uint4 w = *reinterpret_cast<const uint4*>(&g_w16[layer][i * 8]);
        int r = i >> 3;
        int c = (i * 8) & 63;
        *reinterpret_cast<uint4*>(&Wsm[r * ASTRIDE + c]) = w;
    }

    // A tile (128 x 64) -> fp16 smem, fused BN/relu or input-proj
#pragma unroll
    for (int it = 0; it < 8; it++) {
        int idx = tid + it * 256;
        int row = idx >> 4;
        int c4 = (idx & 15) * 4;
        int node = node0 + row;
        float4 v = make_float4(0.f, 0.f, 0.f, 0.f);
        if (node < n) {
            if (layer > 0) {
                v = *reinterpret_cast<const float4*>(&g_agg[node * HDIM + c4]);
                v.x = fmaf(v.x, s_sc[c4 + 0], s_sf[c4 + 0]);
                v.y = fmaf(v.y, s_sc[c4 + 1], s_sf[c4 + 1]);
                v.z = fmaf(v.z, s_sc[c4 + 2], s_sf[c4 + 2]);
                v.w = fmaf(v.w, s_sc[c4 + 3], s_sf[c4 + 3]);
            } else {
                v = *reinterpret_cast<const float4*>(&bin[c4]);
#pragma unroll
                for (int k = 0; k < 5; k++) {
                    float xv = __ldg(&x[node * 5 + k]);
                    float4 w = *reinterpret_cast<const float4*>(&Win[k * HDIM + c4]);
                    v.x = fmaf(xv, w.x, v.x);
                    v.y = fmaf(xv, w.y, v.y);
                    v.z = fmaf(xv, w.z, v.z);
                    v.w = fmaf(xv, w.w, v.w);
                }
            }
            v.x = fmaxf(v.x, 0.f); v.y = fmaxf(v.y, 0.f);
            v.z = fmaxf(v.z, 0.f); v.w = fmaxf(v.w, 0.f);
        }
        __half2 h0 = __floats2half2_rn(v.x, v.y);
        __half2 h1 = __floats2half2_rn(v.z, v.w);
        uint2 pk;
        pk.x = *reinterpret_cast<unsigned*>(&h0);
        pk.y = *reinterpret_cast<unsigned*>(&h1);
        *reinterpret_cast<uint2*>(&Asm[row * ASTRIDE + c4]) = pk;
    }
    __syncthreads();

    int warp = tid >> 5, lane = tid & 31;
    int wrow = warp * 16;

    // A fragments for all 4 k-steps (m16k16 each)
    unsigned a[4][4];
    {
        int r = lane & 15;
        int cb = (lane >> 4) << 3;
#pragma unroll
        for (int ks = 0; ks < 4; ks++) {
            unsigned addr = s2u(&Asm[(wrow + r) * ASTRIDE + ks * 16 + cb]);
            asm volatile("ldmatrix.sync.aligned.m8n8.x4.shared.b16 {%0,%1,%2,%3}, [%4];"
                         : "=r"(a[ks][0]), "=r"(a[ks][1]), "=r"(a[ks][2]), "=r"(a[ks][3])
                         : "r"(addr));
        }
    }

    float acc[8][4];
#pragma unroll
    for (int nt = 0; nt < 8; nt++)
#pragma unroll
        for (int q = 0; q < 4; q++) acc[nt][q] = 0.0f;

#pragma unroll
    for (int nt = 0; nt < 8; nt++) {
#pragma unroll
        for (int ks = 0; ks < 4; ks++) {
            unsigned b0, b1;
            int r = lane & 15;
            unsigned baddr = s2u(&Wsm[(ks * 16 + r) * ASTRIDE + nt * 8]);
            asm volatile("ldmatrix.sync.aligned.m8n8.x2.trans.shared.b16 {%0,%1}, [%2];"
                         : "=r"(b0), "=r"(b1) : "r"(baddr));
            asm volatile(
                "mma.sync.aligned.m16n8k16.row.col.f32.f16.f16.f32 "
                "{%0,%1,%2,%3}, {%4,%5,%6,%7}, {%8,%9}, {%0,%1,%2,%3};"
                : "+f"(acc[nt][0]), "+f"(acc[nt][1]), "+f"(acc[nt][2]), "+f"(acc[nt][3])
                : "r"(a[ks][0]), "r"(a[ks][1]), "r"(a[ks][2]), "r"(a[ks][3]),
                  "r"(b0), "r"(b1));
        }
    }

    // epilogue: scale by dinv, pack fp16, store
    int gr = lane >> 2;
    int qp = lane & 3;
    int node_a = node0 + wrow + gr;
    int node_b = node_a + 8;
    float dia = (node_a < n) ? g_dinv[node_a] : 0.f;
    float dib = (node_b < n) ? g_dinv[node_b] : 0.f;
#pragma unroll
    for (int nt = 0; nt < 8; nt++) {
        if (node_a < n)
            g_hs2[node_a * 32 + nt * 4 + qp] =
                __floats2half2_rn(acc[nt][0] * dia, acc[nt][1] * dia);
        if (node_b < n)
            g_hs2[node_b * 32 + nt * 4 + qp] =
                __floats2half2_rn(acc[nt][2] * dib, acc[nt][3] * dib);
    }
}

// ---------------------------------------------------------------------------
// pull-based aggregation + BN stats. Padded buckets (sentinel n, zero row).
// NODES_PER_WARP=4: doubles grid (3125 blocks) for better wave balance.
#define AGG_WARPS 8
#define NODES_PER_WARP 4
__global__ void k_aggregate(int n, int layer) {
    __shared__ float s_sum[HDIM], s_sq[HDIM];
    int tid = threadIdx.x, lane = tid & 31, warp = tid >> 5;
    if (tid < HDIM) { s_sum[tid] = 0.f; s_sq[tid] = 0.f; }
    __syncthreads();

    float ls0 = 0.f, lq0 = 0.f, ls1 = 0.f, lq1 = 0.f;
    int node0 = (blockIdx.x * AGG_WARPS + warp) * NODES_PER_WARP;

    for (int i = 0; i < NODES_PER_WARP; i++) {
        int node = node0 + i;
        if (node >= n) break;
        int beg = g_row[node], end = g_row[node + 1];
        float a0 = 0.f, a1 = 0.f;
        for (int j = beg; j < end; j += 8) {
            int4 sa = *reinterpret_cast<const int4*>(&g_srcs[j]);
            int4 sb = *reinterpret_cast<const int4*>(&g_srcs[j + 4]);
            float2 f[8];
            f[0] = __half22float2(g_hs2[sa.x * 32 + lane]);
            f[1] = __half22float2(g_hs2[sa.y * 32 + lane]);
            f[2] = __half22float2(g_hs2[sa.z * 32 + lane]);
            f[3] = __half22float2(g_hs2[sa.w * 32 + lane]);
            f[4] = __half22float2(g_hs2[sb.x * 32 + lane]);
            f[5] = __half22float2(g_hs2[sb.y * 32 + lane]);
            f[6] = __half22float2(g_hs2[sb.z * 32 + lane]);
            f[7] = __half22float2(g_hs2[sb.w * 32 + lane]);
#pragma unroll
            for (int u = 0; u < 8; u++) { a0 += f[u].x; a1 += f[u].y; }
        }
        float2 self = __half22float2(g_hs2[node * 32 + lane]);
        float di = g_dinv[node];
        a0 = (a0 + self.x) * di;
        a1 = (a1 + self.y) * di;
        float2 o; o.x = a0; o.y = a1;
        *reinterpret_cast<float2*>(&g_agg[node * HDIM + 2 * lane]) = o;
        ls0 += a0; lq0 = fmaf(a0, a0, lq0);
        ls1 += a1; lq1 = fmaf(a1, a1, lq1);
    }

    atomicAdd(&s_sum[2 * lane], ls0);
    atomicAdd(&s_sq[2 * lane], lq0);
    atomicAdd(&s_sum[2 * lane + 1], ls1);
    atomicAdd(&s_sq[2 * lane + 1], lq1);
    __syncthreads();
    if (tid < HDIM) {
        atomicAdd(&g_stats[layer][tid], s_sum[tid]);
        atomicAdd(&g_stats[layer][HDIM + tid], s_sq[tid]);
    }
}

// ---------------------------------------------------------------------------
// classifier with in-block final BN+ReLU: out = relu(bn(agg) @ W1 + b1) @ W2 + b2
__global__ void k_classifier(const float* __restrict__ W1,
                             const float* __restrict__ b1,
                             const float* __restrict__ W2,
                             const float* __restrict__ b2,
                             const float* __restrict__ gamma,
                             const float* __restrict__ beta,
                             float* __restrict__ out, int n) {
    __shared__ float W1sm[HDIM * HC];
    __shared__ float s_sc[HDIM], s_sf[HDIM];
    int tid = threadIdx.x;
    if (tid < HDIM) {
        float inv_n = 1.0f / (float)n;
        float mean = g_stats[NLAYERS - 1][tid] * inv_n;
        float var = g_stats[NLAYERS - 1][HDIM + tid] * inv_n - mean * mean;
        float inv = rsqrtf(var + BN_EPS);
        float sc = gamma[tid] * inv;
        s_sc[tid] = sc;
        s_sf[tid] = beta[tid] - mean * sc;
    }
#pragma unroll
    for (int i = tid; i < HDIM * HC; i += 256) W1sm[i] = W1[i];
    __syncthreads();

    int lane = tid & 31;
    int warp = tid >> 5;
    float b1v = b1[lane];
    float w2v = W2[lane];
    float b2v = b2[0];
    float sc0 = s_sc[lane],      sf0 = s_sf[lane];
    float sc1 = s_sc[lane + 32], sf1 = s_sf[lane + 32];
    int base = blockIdx.x * 64 + warp * 8;

    for (int i = 0; i < 8; i++) {
        int node = base + i;
        if (node >= n) break;
        float h0 = fmaxf(fmaf(g_agg[node * HDIM + lane],      sc0, sf0), 0.f);
        float h1 = fmaxf(fmaf(g_agg[node * HDIM + 32 + lane], sc1, sf1), 0.f);
        float acc = b1v;
#pragma unroll
        for (int k = 0; k < 32; k++)
            acc = fmaf(__shfl_sync(0xFFFFFFFFu, h0, k), W1sm[k * HC + lane], acc);
#pragma unroll
        for (int k = 0; k < 32; k++)
            acc = fmaf(__shfl_sync(0xFFFFFFFFu, h1, k), W1sm[(k + 32) * HC + lane], acc);
        float r = fmaxf(acc, 0.0f) * w2v;
#pragma unroll
        for (int off = 16; off > 0; off >>= 1)
            r += __shfl_xor_sync(0xFFFFFFFFu, r, off);
        if (lane == 0) out[node] = r + b2v;
    }
}

// ---------------------------------------------------------------------------
extern "C" void kernel_launch(void* const* d_in, const int* in_sizes, int n_in,
                              void* d_out, int out_size) {
    const float* x        = (const float*)d_in[0];
    const int*   ei       = (const int*)d_in[1];
    const float* W_in     = (const float*)d_in[2];
    const float* b_in     = (const float*)d_in[3];
    const float* conv_W   = (const float*)d_in[4];
    // d_in[5] = conv_b : cancels exactly inside BatchNorm -> unused
    const float* bn_gamma = (const float*)d_in[6];
    const float* bn_beta  = (const float*)d_in[7];
    const float* W1       = (const float*)d_in[8];
    const float* b1       = (const float*)d_in[9];
    const float* W2       = (const float*)d_in[10];
    const float* b2       = (const float*)d_in[11];
    float* out = (float*)d_out;

    int n = in_sizes[0] / 5;
    int e = in_sizes[1] / 2;
    int nb = (n + SCAN_BLK - 1) / SCAN_BLK;

    k_count_deg<<<(e + 255) / 256, 256>>>(ei + e, e, n, conv_W);
    k_scan_fused<<<nb, 256>>>(n);
    k_bucket<<<(e + 255) / 256, 256>>>(ei, e, n);

    int gemm_blocks = (n + GROWS - 1) / GROWS;
    int agg_blocks = (n + AGG_WARPS * NODES_PER_WARP - 1) / (AGG_WARPS * NODES_PER_WARP);

    for (int l = 0; l < NLAYERS; l++) {
        k_gemm_mma<<<gemm_blocks, 256>>>(
            n, l, x, W_in, b_in,
            l > 0 ? bn_gamma + (l - 1) * HDIM : nullptr,
            l > 0 ? bn_beta + (l - 1) * HDIM : nullptr);
        k_aggregate<<<agg_blocks, 256>>>(n, l);
    }

    k_classifier<<<(n + 63) / 64, 256>>>(
        W1, b1, W2, b2,
        bn_gamma + (NLAYERS - 1) * HDIM, bn_beta + (NLAYERS - 1) * HDIM, out, n);
}